// round 10
// baseline (speedup 1.0000x reference)
#include <cuda_runtime.h>
#include <cuda_fp16.h>
#include <math.h>

// Problem constants
#define B_  2
#define T_  2048
#define C_  1024
#define H_  16
#define D_  64
#define M_  (B_*T_)          // 4096
#define N3_ (3*C_)           // 3072

// NO __device__ globals, NO static initializers, NO CUDA calls outside
// kernel_launch. All scratch lives inside d_out (16 MiB), viewed as "strips":
// row m, strip s occupies half-elements [m*2048 + s*128, +128): 64 fp16 (K or
// other) + 64 fp16 (V or other). Zero local memory everywhere (only
// __expf/__sincosf/rsqrtf intrinsics; all arrays constant-indexed).

// y placement map (head -> strip, half) used by flash epilogue and proj:
__device__ __forceinline__ int ystrip_of(int h) {
    return (h < 2) ? 15 : ((h == 15) ? 8 : ((h - 2) >> 1));
}
__device__ __forceinline__ int yhalf_of(int h) {
    return (h == 15) ? 0 : (h & 1);
}

// ---------------------------------------------------------------------------
// KV kernel: for head h (= hbase + bx>>1), kind (bx&1: 0=K,1=V), one 128-row
// tile: GEMM x @ W_attn[:, n0:n0+64] + bias; K gets RMS-norm + head-indexed
// rotary; both stored fp16 into strip s = (h==15 ? 7 : h).
// ---------------------------------------------------------------------------
__global__ __launch_bounds__(256) void kv16_kernel(
    const float* __restrict__ x, const float* __restrict__ Wa,
    const float* __restrict__ ba, half* __restrict__ Hbuf, int hbase)
{
    __shared__ float As[16][132];
    __shared__ float Bs[16][64];

    const int tid  = threadIdx.x;
    const int tx   = tid & 15;
    const int ty   = tid >> 4;
    const int m0   = blockIdx.y * 128;
    const int h    = hbase + (blockIdx.x >> 1);
    const int kind = blockIdx.x & 1;              // 0=K, 1=V
    const int s    = (h == 15) ? 7 : h;
    const int n0   = (kind ? 2 * C_ : C_) + h * 64;

    float acc[8][4];
    #pragma unroll
    for (int r = 0; r < 8; r++)
        #pragma unroll
        for (int c = 0; c < 4; c++) acc[r][c] = 0.f;

    for (int k0 = 0; k0 < C_; k0 += 16) {
        #pragma unroll
        for (int i = 0; i < 2; i++) {
            int f   = tid + i * 256;
            int row = f >> 2;
            int kc  = (f & 3) * 4;
            float4 a4 = *(const float4*)&x[(size_t)(m0 + row) * C_ + k0 + kc];
            As[kc + 0][row] = a4.x;
            As[kc + 1][row] = a4.y;
            As[kc + 2][row] = a4.z;
            As[kc + 3][row] = a4.w;
        }
        *(float4*)&Bs[ty][tx * 4] =
            *(const float4*)&Wa[(size_t)(k0 + ty) * N3_ + n0 + tx * 4];
        __syncthreads();

        #pragma unroll
        for (int k = 0; k < 16; k++) {
            float4 b4 = *(float4*)&Bs[k][tx * 4];
            float4 a0 = *(float4*)&As[k][ty * 8];
            float4 a1 = *(float4*)&As[k][ty * 8 + 4];
            float a[8] = {a0.x, a0.y, a0.z, a0.w, a1.x, a1.y, a1.z, a1.w};
            #pragma unroll
            for (int r = 0; r < 8; r++) {
                acc[r][0] += a[r] * b4.x;
                acc[r][1] += a[r] * b4.y;
                acc[r][2] += a[r] * b4.z;
                acc[r][3] += a[r] * b4.w;
            }
        }
        __syncthreads();
    }

    float4 bv = *(const float4*)&ba[n0 + tx * 4];
    const float bias_c[4] = {bv.x, bv.y, bv.z, bv.w};

    if (kind == 1) {
        // V: plain fp16 store into strip half 1
        #pragma unroll
        for (int r = 0; r < 8; r++) {
            const size_t idx = (size_t)(m0 + ty * 8 + r) * 2048 + s * 128 + 64 + tx * 4;
            *(half2*)&Hbuf[idx]     = __floats2half2_rn(acc[r][0] + bias_c[0], acc[r][1] + bias_c[1]);
            *(half2*)&Hbuf[idx + 2] = __floats2half2_rn(acc[r][2] + bias_c[2], acc[r][3] + bias_c[3]);
        }
        return;
    }

    // K: RMS-norm + rotary (angle = h * 10000^(-j/32), j = (tx&7)*4 + c)
    float csv[4], snv[4];
    #pragma unroll
    for (int c = 0; c < 4; c++) {
        int j = ((tx & 7) * 4) + c;
        float ang = (float)h * __expf(-(float)j * 0.28782313662425572f);
        __sincosf(ang, &snv[c], &csv[c]);
    }
    const bool lo_half = (tx < 8);

    #pragma unroll
    for (int r = 0; r < 8; r++) {
        float v0 = acc[r][0] + bias_c[0];
        float v1 = acc[r][1] + bias_c[1];
        float v2 = acc[r][2] + bias_c[2];
        float v3 = acc[r][3] + bias_c[3];

        float ss = v0 * v0 + v1 * v1 + v2 * v2 + v3 * v3;
        ss += __shfl_xor_sync(~0u, ss, 1);
        ss += __shfl_xor_sync(~0u, ss, 2);
        ss += __shfl_xor_sync(~0u, ss, 4);
        ss += __shfl_xor_sync(~0u, ss, 8);
        float sc = rsqrtf(ss * (1.0f / 64.0f) + 1.1920929e-07f);
        v0 *= sc; v1 *= sc; v2 *= sc; v3 *= sc;

        float p0 = __shfl_xor_sync(~0u, v0, 8);
        float p1 = __shfl_xor_sync(~0u, v1, 8);
        float p2 = __shfl_xor_sync(~0u, v2, 8);
        float p3 = __shfl_xor_sync(~0u, v3, 8);

        float o0, o1, o2, o3;
        if (lo_half) {
            o0 = v0 * csv[0] + p0 * snv[0];
            o1 = v1 * csv[1] + p1 * snv[1];
            o2 = v2 * csv[2] + p2 * snv[2];
            o3 = v3 * csv[3] + p3 * snv[3];
        } else {
            o0 = v0 * csv[0] - p0 * snv[0];
            o1 = v1 * csv[1] - p1 * snv[1];
            o2 = v2 * csv[2] - p2 * snv[2];
            o3 = v3 * csv[3] - p3 * snv[3];
        }

        const size_t idx = (size_t)(m0 + ty * 8 + r) * 2048 + s * 128 + tx * 4;
        *(half2*)&Hbuf[idx]     = __floats2half2_rn(o0, o1);
        *(half2*)&Hbuf[idx + 2] = __floats2half2_rn(o2, o3);
    }
}

// ---------------------------------------------------------------------------
// Flash kernel, one head per blockIdx.z (h = hbase + z), batch = blockIdx.y,
// q-tile = blockIdx.x. Recomputes its 64-row Q tile (GEMM+RMS+rope) from x,
// reads fp16 K/V strips, runs causal online-softmax flash, writes y fp16
// into the mapped half-strip. Static smem exactly 48 KB (3x 64x64 fp32);
// the Q-GEMM's staging tiles alias the K and V buffers (dead at that time).
// ---------------------------------------------------------------------------
__global__ __launch_bounds__(256) void flash_kernel(
    const float* __restrict__ x, const float* __restrict__ Wa,
    const float* __restrict__ ba, half* __restrict__ Hbuf, int hbase)
{
    __shared__ float S[3 * 64 * 64];      // 48 KB
    float* Qs = S;                        // [d][q]  (stride 64)
    float* KP = S + 4096;                 // K^T [d][k], then P [q][j]
    float* Vs = S + 8192;                 // V [j][d]

    const int tid = threadIdx.x;
    const int tx  = tid & 15;             // col micro / k micro (kx)
    const int ty  = tid >> 4;             // row micro / q micro (qy)
    const int h   = hbase + blockIdx.z;
    const int b   = blockIdx.y;
    const int q0  = blockIdx.x * 64;
    const int m0  = b * 2048 + q0;
    const int kvs = (h == 15) ? 7 : h;
    const int ys  = ystrip_of(h);
    const int yh  = yhalf_of(h);

    // ---- Q recompute: q[64 x 64] = x[m0..][*] @ Wa[:, h*64..] + bias ----
    {
        float (*As)[68] = (float(*)[68])KP;     // 16x68 aliased into KP
        float (*Ws)[64] = (float(*)[64])Vs;     // 16x64 aliased into Vs

        float acc[4][4];
        #pragma unroll
        for (int r = 0; r < 4; r++)
            #pragma unroll
            for (int c = 0; c < 4; c++) acc[r][c] = 0.f;

        const int nq = h * 64;
        for (int k0 = 0; k0 < C_; k0 += 16) {
            {
                int row = tid >> 2;
                int kc  = (tid & 3) * 4;
                float4 a4 = *(const float4*)&x[(size_t)(m0 + row) * C_ + k0 + kc];
                As[kc + 0][row] = a4.x;
                As[kc + 1][row] = a4.y;
                As[kc + 2][row] = a4.z;
                As[kc + 3][row] = a4.w;
            }
            *(float4*)&Ws[ty][tx * 4] =
                *(const float4*)&Wa[(size_t)(k0 + ty) * N3_ + nq + tx * 4];
            __syncthreads();

            #pragma unroll
            for (int k = 0; k < 16; k++) {
                float4 b4 = *(float4*)&Ws[k][tx * 4];
                float4 a4 = *(float4*)&As[k][ty * 4];
                float a[4] = {a4.x, a4.y, a4.z, a4.w};
                #pragma unroll
                for (int r = 0; r < 4; r++) {
                    acc[r][0] += a[r] * b4.x;
                    acc[r][1] += a[r] * b4.y;
                    acc[r][2] += a[r] * b4.z;
                    acc[r][3] += a[r] * b4.w;
                }
            }
            __syncthreads();
        }

        // RMS-norm + rotary + 1/8 scale, write transposed into Qs[d][q]
        float4 bv = *(const float4*)&ba[nq + tx * 4];
        const float bias_c[4] = {bv.x, bv.y, bv.z, bv.w};
        float csv[4], snv[4];
        #pragma unroll
        for (int c = 0; c < 4; c++) {
            int j = ((tx & 7) * 4) + c;
            float ang = (float)h * __expf(-(float)j * 0.28782313662425572f);
            __sincosf(ang, &snv[c], &csv[c]);
        }
        const bool lo_half = (tx < 8);

        #pragma unroll
        for (int r = 0; r < 4; r++) {
            float v0 = acc[r][0] + bias_c[0];
            float v1 = acc[r][1] + bias_c[1];
            float v2 = acc[r][2] + bias_c[2];
            float v3 = acc[r][3] + bias_c[3];

            float ss = v0 * v0 + v1 * v1 + v2 * v2 + v3 * v3;
            ss += __shfl_xor_sync(~0u, ss, 1);
            ss += __shfl_xor_sync(~0u, ss, 2);
            ss += __shfl_xor_sync(~0u, ss, 4);
            ss += __shfl_xor_sync(~0u, ss, 8);
            float sc = rsqrtf(ss * (1.0f / 64.0f) + 1.1920929e-07f);
            v0 *= sc; v1 *= sc; v2 *= sc; v3 *= sc;

            float p0 = __shfl_xor_sync(~0u, v0, 8);
            float p1 = __shfl_xor_sync(~0u, v1, 8);
            float p2 = __shfl_xor_sync(~0u, v2, 8);
            float p3 = __shfl_xor_sync(~0u, v3, 8);

            float o0, o1, o2, o3;
            if (lo_half) {
                o0 = v0 * csv[0] + p0 * snv[0];
                o1 = v1 * csv[1] + p1 * snv[1];
                o2 = v2 * csv[2] + p2 * snv[2];
                o3 = v3 * csv[3] + p3 * snv[3];
            } else {
                o0 = v0 * csv[0] - p0 * snv[0];
                o1 = v1 * csv[1] - p1 * snv[1];
                o2 = v2 * csv[2] - p2 * snv[2];
                o3 = v3 * csv[3] - p3 * snv[3];
            }
            const int q = ty * 4 + r;
            Qs[(tx * 4 + 0) * 64 + q] = o0 * 0.125f;
            Qs[(tx * 4 + 1) * 64 + q] = o1 * 0.125f;
            Qs[(tx * 4 + 2) * 64 + q] = o2 * 0.125f;
            Qs[(tx * 4 + 3) * 64 + q] = o3 * 0.125f;
        }
    }

    // ---- flash mainloop ----
    float m[4], l[4], o[4][4];
    #pragma unroll
    for (int qq = 0; qq < 4; qq++) {
        m[qq] = -1e30f; l[qq] = 0.f;
        #pragma unroll
        for (int dd = 0; dd < 4; dd++) o[qq][dd] = 0.f;
    }

    const int ntiles = blockIdx.x + 1;
    for (int it = 0; it < ntiles; it++) {
        const int k0 = it * 64;
        const int mk = b * 2048 + k0;
        __syncthreads();   // Qs ready (it=0) / prev P,V reads done

        // Load K (transposed to KP[d][k]) and V (Vs[j][d]) from fp16 strips
        #pragma unroll
        for (int i = 0; i < 8; i++) {
            int f   = tid + i * 256;          // 0..2047
            int row = f >> 5;                 // 0..63
            int c2  = f & 31;                 // half2 index
            const size_t base = (size_t)(mk + row) * 2048 + kvs * 128;
            half2 kk = *(const half2*)&Hbuf[base + c2 * 2];
            half2 vv = *(const half2*)&Hbuf[base + 64 + c2 * 2];
            KP[(2 * c2 + 0) * 64 + row] = __half2float(__low2half(kk));
            KP[(2 * c2 + 1) * 64 + row] = __half2float(__high2half(kk));
            Vs[row * 64 + 2 * c2 + 0]   = __half2float(__low2half(vv));
            Vs[row * 64 + 2 * c2 + 1]   = __half2float(__high2half(vv));
        }
        __syncthreads();

        float s[4][4];
        #pragma unroll
        for (int qq = 0; qq < 4; qq++)
            #pragma unroll
            for (int kk = 0; kk < 4; kk++) s[qq][kk] = 0.f;

        #pragma unroll 16
        for (int d = 0; d < 64; d++) {
            float4 a  = *(float4*)&Qs[d * 64 + ty * 4];
            float4 bb = *(float4*)&KP[d * 64 + tx * 4];
            float av[4] = {a.x, a.y, a.z, a.w};
            float bvv[4] = {bb.x, bb.y, bb.z, bb.w};
            #pragma unroll
            for (int qq = 0; qq < 4; qq++)
                #pragma unroll
                for (int kk = 0; kk < 4; kk++) s[qq][kk] += av[qq] * bvv[kk];
        }

        if (k0 == q0) {
            #pragma unroll
            for (int qq = 0; qq < 4; qq++)
                #pragma unroll
                for (int kk = 0; kk < 4; kk++)
                    if (tx * 4 + kk > ty * 4 + qq) s[qq][kk] = -1e30f;
        }

        #pragma unroll
        for (int qq = 0; qq < 4; qq++) {
            float mx = fmaxf(fmaxf(s[qq][0], s[qq][1]), fmaxf(s[qq][2], s[qq][3]));
            #pragma unroll
            for (int off = 8; off; off >>= 1)
                mx = fmaxf(mx, __shfl_xor_sync(~0u, mx, off));
            float mnew  = fmaxf(m[qq], mx);
            float alpha = __expf(m[qq] - mnew);
            float rs = 0.f;
            #pragma unroll
            for (int kk = 0; kk < 4; kk++) {
                float p = __expf(s[qq][kk] - mnew);
                s[qq][kk] = p;
                rs += p;
            }
            #pragma unroll
            for (int off = 8; off; off >>= 1)
                rs += __shfl_xor_sync(~0u, rs, off);
            l[qq] = l[qq] * alpha + rs;
            m[qq] = mnew;
            #pragma unroll
            for (int dd = 0; dd < 4; dd++) o[qq][dd] *= alpha;
        }
        __syncthreads();   // all K reads done

        #pragma unroll
        for (int qq = 0; qq < 4; qq++)
            *(float4*)&KP[(ty * 4 + qq) * 64 + tx * 4] =
                make_float4(s[qq][0], s[qq][1], s[qq][2], s[qq][3]);
        __syncthreads();

        #pragma unroll 4
        for (int j0 = 0; j0 < 64; j0 += 4) {
            float pr[4][4];
            #pragma unroll
            for (int qq = 0; qq < 4; qq++) {
                float4 p4 = *(float4*)&KP[(ty * 4 + qq) * 64 + j0];
                pr[qq][0] = p4.x; pr[qq][1] = p4.y; pr[qq][2] = p4.z; pr[qq][3] = p4.w;
            }
            #pragma unroll
            for (int jj = 0; jj < 4; jj++) {
                float4 vv = *(float4*)&Vs[(j0 + jj) * 64 + tx * 4];
                #pragma unroll
                for (int qq = 0; qq < 4; qq++) {
                    o[qq][0] += pr[qq][jj] * vv.x;
                    o[qq][1] += pr[qq][jj] * vv.y;
                    o[qq][2] += pr[qq][jj] * vv.z;
                    o[qq][3] += pr[qq][jj] * vv.w;
                }
            }
        }
    }

    // Epilogue: normalize, fp16, write to mapped half-strip
    #pragma unroll
    for (int qq = 0; qq < 4; qq++) {
        float inv = 1.0f / l[qq];
        const size_t mrow = (size_t)(b * 2048 + q0 + ty * 4 + qq);
        const size_t idx  = mrow * 2048 + ys * 128 + yh * 64 + tx * 4;
        *(half2*)&Hbuf[idx]     = __floats2half2_rn(o[qq][0] * inv, o[qq][1] * inv);
        *(half2*)&Hbuf[idx + 2] = __floats2half2_rn(o[qq][2] * inv, o[qq][3] * inv);
    }
}

// ---------------------------------------------------------------------------
// In-place projection: block handles 32 rows. Gathers its rows' y (fp16,
// from the strip map) into smem, syncs, then overwrites those same d_out rows
// with fp32 y @ W_proj + b_proj. Read set == own write set -> race-free.
// Dynamic smem: 32*1024 halfs (64 KB) + 16*128 floats (8 KB) = 72 KB.
// ---------------------------------------------------------------------------
__global__ __launch_bounds__(256) void proj_kernel(
    const float* __restrict__ Wp, const float* __restrict__ bp,
    float* __restrict__ out)
{
    extern __shared__ char smem_raw[];
    half*  ysm = (half*)smem_raw;                       // [32][1024]
    float* Wt  = (float*)(smem_raw + 32 * 1024 * 2);    // [16][128]

    const half* Hbuf = (const half*)out;
    const int tid = threadIdx.x;
    const int tx  = tid & 31;          // 32 col groups of 4
    const int ty  = tid >> 5;          // 8 row groups of 4
    const int m0  = blockIdx.x * 32;

    // Gather y rows (all 16 heads) into smem
    #pragma unroll
    for (int i = 0; i < 64; i++) {
        int f  = tid + i * 256;        // 0..16383 half2 items
        int r  = f >> 9;               // row 0..31
        int c2 = f & 511;              // half2 col
        int h  = c2 >> 5;
        int d2 = c2 & 31;
        int ys = ystrip_of(h);
        int yh = yhalf_of(h);
        half2 v = *(const half2*)&Hbuf[(size_t)(m0 + r) * 2048 + ys * 128 + yh * 64 + d2 * 2];
        *(half2*)&ysm[r * 1024 + c2 * 2] = v;
    }
    __syncthreads();

    for (int nt = 0; nt < 8; nt++) {
        float acc[4][4];
        #pragma unroll
        for (int r = 0; r < 4; r++)
            #pragma unroll
            for (int c = 0; c < 4; c++) acc[r][c] = 0.f;

        for (int k0 = 0; k0 < C_; k0 += 16) {
            __syncthreads();   // guard Wt overwrite vs prior reads
            #pragma unroll
            for (int i = 0; i < 2; i++) {
                int f   = tid + i * 256;     // 0..511 float4 items
                int row = f >> 5;
                int c4  = (f & 31) * 4;
                *(float4*)&Wt[row * 128 + c4] =
                    *(const float4*)&Wp[(size_t)(k0 + row) * C_ + nt * 128 + c4];
            }
            __syncthreads();

            #pragma unroll
            for (int k = 0; k < 16; k++) {
                float4 b4 = *(float4*)&Wt[k * 128 + tx * 4];
                float a[4];
                #pragma unroll
                for (int r = 0; r < 4; r++)
                    a[r] = __half2float(ysm[(ty * 4 + r) * 1024 + k0 + k]);
                #pragma unroll
                for (int r = 0; r < 4; r++) {
                    acc[r][0] += a[r] * b4.x;
                    acc[r][1] += a[r] * b4.y;
                    acc[r][2] += a[r] * b4.z;
                    acc[r][3] += a[r] * b4.w;
                }
            }
        }

        float4 bb = *(const float4*)&bp[nt * 128 + tx * 4];
        #pragma unroll
        for (int r = 0; r < 4; r++) {
            float4 outv;
            outv.x = acc[r][0] + bb.x;
            outv.y = acc[r][1] + bb.y;
            outv.z = acc[r][2] + bb.z;
            outv.w = acc[r][3] + bb.w;
            *(float4*)&out[(size_t)(m0 + ty * 4 + r) * C_ + nt * 128 + tx * 4] = outv;
        }
    }
}

// ---------------------------------------------------------------------------
extern "C" void kernel_launch(void* const* d_in, const int* in_sizes, int n_in,
                              void* d_out, int out_size)
{
    const float* x      = (const float*)d_in[0];
    const float* W_attn = (const float*)d_in[1];
    const float* b_attn = (const float*)d_in[2];
    const float* W_proj = (const float*)d_in[3];
    const float* b_proj = (const float*)d_in[4];
    float* out  = (float*)d_out;
    half*  Hbuf = (half*)d_out;

    // Phase 1: K,V fp16 for heads 0..14 -> strips 0..14 (strip 15 reserved)
    kv16_kernel<<<dim3(30, 32), 256>>>(x, W_attn, b_attn, Hbuf, 0);

    // Phase 2: flash in dependency-safe waves (y lands in freed half-strips)
    flash_kernel<<<dim3(32, 2, 2), 256>>>(x, W_attn, b_attn, Hbuf, 0);   // h 0..1  -> y in strip 15
    flash_kernel<<<dim3(32, 2, 4), 256>>>(x, W_attn, b_attn, Hbuf, 2);   // h 2..5  -> y in strips 0..1
    flash_kernel<<<dim3(32, 2, 8), 256>>>(x, W_attn, b_attn, Hbuf, 6);   // h 6..13 -> y in strips 2..5
    // K,V for head 15 into strip 7 (dead after wave above)
    kv16_kernel<<<dim3(2, 32), 256>>>(x, W_attn, b_attn, Hbuf, 15);
    flash_kernel<<<dim3(32, 2, 2), 256>>>(x, W_attn, b_attn, Hbuf, 14);  // h 14,15 -> y in 6K, 8K

    // Phase 3: in-place projection (72 KB dynamic smem)
    cudaFuncSetAttribute(proj_kernel, cudaFuncAttributeMaxDynamicSharedMemorySize, 73728);
    proj_kernel<<<128, 256, 73728>>>(W_proj, b_proj, out);
}

// round 12
// speedup vs baseline: 1.9439x; 1.9439x over previous
#include <cuda_runtime.h>
#include <cuda_fp16.h>
#include <math.h>

// Problem constants
#define B_  2
#define T_  2048
#define C_  1024
#define H_  16
#define D_  64
#define M_  (B_*T_)          // 4096
#define N3_ (3*C_)           // 3072

// NO __device__ globals, NO static initializers (R2-R10: any module data
// segment triggers a 128 MiB driver slab inside the checkpointed run).
// All scratch lives in d_out (16 MiB = 4096 rows x 2048 halfs), in "strips":
// strip s of row m = halfs [m*2048 + s*128, +128).
//
// 3 head-waves {6,6,4}. Per wave (local head hl, global h = hbase+hl):
//   K fp16 -> strip hl,        offset 0   (normed+roped)
//   V fp16 -> strip hl,        offset 64
//   Q fp16 -> strip 6+(hl>>1), offset (hl&1)*64  (normed+roped, x0.125)
//   y fp16 -> strip 15-(h>>1), offset (h&1)*64   (persistent across waves)
// Wave0 y: s15,14,13; wave1: s12,11,10; wave2: s9,8. Strip 8 is Q-only in
// waves 0-1 and y-only in wave 2 -> no live-region collision anywhere.

// ---------------------------------------------------------------------------
// kvq: fused QKV GEMM + bias (+ RMS-norm + head-indexed rotary for K and Q)
// for one wave. Tiles 128(M) x 64(N) x 16(K), 256 threads, 8x4 micro-tile.
// bx = hl*3 + kind (kind: 0=K, 1=V, 2=Q).
// ---------------------------------------------------------------------------
__global__ __launch_bounds__(256) void kvq_kernel(
    const float* __restrict__ x, const float* __restrict__ Wa,
    const float* __restrict__ ba, half* __restrict__ Hbuf, int hbase)
{
    __shared__ float As[16][132];
    __shared__ float Bs[16][64];

    const int tid  = threadIdx.x;
    const int tx   = tid & 15;
    const int ty   = tid >> 4;
    const int m0   = blockIdx.y * 128;
    const int hl   = blockIdx.x / 3;
    const int kind = blockIdx.x % 3;              // 0=K, 1=V, 2=Q
    const int h    = hbase + hl;
    const int n0   = (kind == 0 ? C_ : (kind == 1 ? 2 * C_ : 0)) + h * 64;
    // destination strip/offset
    const int s    = (kind == 2) ? (6 + (hl >> 1)) : hl;
    const int off  = (kind == 2) ? ((hl & 1) * 64) : (kind == 1 ? 64 : 0);

    float acc[8][4];
    #pragma unroll
    for (int r = 0; r < 8; r++)
        #pragma unroll
        for (int c = 0; c < 4; c++) acc[r][c] = 0.f;

    for (int k0 = 0; k0 < C_; k0 += 16) {
        #pragma unroll
        for (int i = 0; i < 2; i++) {
            int f   = tid + i * 256;
            int row = f >> 2;
            int kc  = (f & 3) * 4;
            float4 a4 = *(const float4*)&x[(size_t)(m0 + row) * C_ + k0 + kc];
            As[kc + 0][row] = a4.x;
            As[kc + 1][row] = a4.y;
            As[kc + 2][row] = a4.z;
            As[kc + 3][row] = a4.w;
        }
        *(float4*)&Bs[ty][tx * 4] =
            *(const float4*)&Wa[(size_t)(k0 + ty) * N3_ + n0 + tx * 4];
        __syncthreads();

        #pragma unroll
        for (int k = 0; k < 16; k++) {
            float4 b4 = *(float4*)&Bs[k][tx * 4];
            float4 a0 = *(float4*)&As[k][ty * 8];
            float4 a1 = *(float4*)&As[k][ty * 8 + 4];
            float a[8] = {a0.x, a0.y, a0.z, a0.w, a1.x, a1.y, a1.z, a1.w};
            #pragma unroll
            for (int r = 0; r < 8; r++) {
                acc[r][0] += a[r] * b4.x;
                acc[r][1] += a[r] * b4.y;
                acc[r][2] += a[r] * b4.z;
                acc[r][3] += a[r] * b4.w;
            }
        }
        __syncthreads();
    }

    float4 bv = *(const float4*)&ba[n0 + tx * 4];
    const float bias_c[4] = {bv.x, bv.y, bv.z, bv.w};

    if (kind == 1) {
        // V: plain fp16 store
        #pragma unroll
        for (int r = 0; r < 8; r++) {
            const size_t idx = (size_t)(m0 + ty * 8 + r) * 2048 + s * 128 + off + tx * 4;
            *(half2*)&Hbuf[idx]     = __floats2half2_rn(acc[r][0] + bias_c[0], acc[r][1] + bias_c[1]);
            *(half2*)&Hbuf[idx + 2] = __floats2half2_rn(acc[r][2] + bias_c[2], acc[r][3] + bias_c[3]);
        }
        return;
    }

    // K/Q: RMS-norm + rotary (angle = h * 10000^(-j/32), j = (tx&7)*4 + c)
    float csv[4], snv[4];
    #pragma unroll
    for (int c = 0; c < 4; c++) {
        int j = ((tx & 7) * 4) + c;
        float ang = (float)h * __expf(-(float)j * 0.28782313662425572f);
        __sincosf(ang, &snv[c], &csv[c]);
    }
    const float scale = (kind == 2) ? 0.125f : 1.0f;
    const bool lo_half = (tx < 8);

    #pragma unroll
    for (int r = 0; r < 8; r++) {
        float v0 = acc[r][0] + bias_c[0];
        float v1 = acc[r][1] + bias_c[1];
        float v2 = acc[r][2] + bias_c[2];
        float v3 = acc[r][3] + bias_c[3];

        float ss = v0 * v0 + v1 * v1 + v2 * v2 + v3 * v3;
        ss += __shfl_xor_sync(~0u, ss, 1);
        ss += __shfl_xor_sync(~0u, ss, 2);
        ss += __shfl_xor_sync(~0u, ss, 4);
        ss += __shfl_xor_sync(~0u, ss, 8);
        float sc = rsqrtf(ss * (1.0f / 64.0f) + 1.1920929e-07f);
        v0 *= sc; v1 *= sc; v2 *= sc; v3 *= sc;

        float p0 = __shfl_xor_sync(~0u, v0, 8);
        float p1 = __shfl_xor_sync(~0u, v1, 8);
        float p2 = __shfl_xor_sync(~0u, v2, 8);
        float p3 = __shfl_xor_sync(~0u, v3, 8);

        float o0, o1, o2, o3;
        if (lo_half) {
            o0 = v0 * csv[0] + p0 * snv[0];
            o1 = v1 * csv[1] + p1 * snv[1];
            o2 = v2 * csv[2] + p2 * snv[2];
            o3 = v3 * csv[3] + p3 * snv[3];
        } else {
            o0 = v0 * csv[0] - p0 * snv[0];
            o1 = v1 * csv[1] - p1 * snv[1];
            o2 = v2 * csv[2] - p2 * snv[2];
            o3 = v3 * csv[3] - p3 * snv[3];
        }

        const size_t idx = (size_t)(m0 + ty * 8 + r) * 2048 + s * 128 + off + tx * 4;
        *(half2*)&Hbuf[idx]     = __floats2half2_rn(o0 * scale, o1 * scale);
        *(half2*)&Hbuf[idx + 2] = __floats2half2_rn(o2 * scale, o3 * scale);
    }
}

// ---------------------------------------------------------------------------
// mma helper: m16n8k16 row.col f32 = f16 x f16 + f32
// ---------------------------------------------------------------------------
__device__ __forceinline__ void mma16816(
    float c[4], const unsigned a[4], unsigned b0, unsigned b1)
{
    asm volatile(
        "mma.sync.aligned.m16n8k16.row.col.f32.f16.f16.f32 "
        "{%0,%1,%2,%3}, {%4,%5,%6,%7}, {%8,%9}, {%0,%1,%2,%3};"
        : "+f"(c[0]), "+f"(c[1]), "+f"(c[2]), "+f"(c[3])
        : "r"(a[0]), "r"(a[1]), "r"(a[2]), "r"(a[3]), "r"(b0), "r"(b1));
}

// ---------------------------------------------------------------------------
// Tensor-core causal flash for one wave. Block = (q-tile, batch, hl);
// 256 threads = 8 warps in a 4(q) x 2(k/d) warp grid. Q loaded fp16 from
// strips (A fragments held in registers across all kv tiles); K key-major and
// V d-major (transposed) in smem so all fragment halves are contiguous half2
// at canonical m16n8k16 lane coordinates (stride 72 halfs: conflict-free).
// In-register online softmax with quad shuffles + cross-warp-pair smem
// combine; P fp16 via smem; O accumulates in fp32 fragments.
// ---------------------------------------------------------------------------
__global__ __launch_bounds__(256) void flash_mma(half* __restrict__ Hbuf, int hbase)
{
    __shared__ half Qh[64 * 72];
    __shared__ half Kh[64 * 72];
    __shared__ half Vt[64 * 72];   // transposed: Vt[d][j]
    __shared__ half Ph[64 * 72];
    __shared__ float redm[2][64];
    __shared__ float reds[2][64];

    const int tid  = threadIdx.x;
    const int lane = tid & 31;
    const int w    = tid >> 5;
    const int gid  = lane >> 2;          // group id (row within fragment)
    const int tq   = lane & 3;           // thread-in-group (col pair)
    const int wq   = (w >> 1) * 16;      // warp q offset
    const int wk   = (w & 1) * 32;       // warp k/d offset
    const int wc   = w & 1;              // warp column (for reductions)

    const int hl = blockIdx.z;
    const int h  = hbase + hl;
    const int b  = blockIdx.y;
    const int q0 = blockIdx.x * 64;
    const int kvs = hl;
    const int qs  = 6 + (hl >> 1);
    const int qoff = (hl & 1) * 64;
    const int ys  = 15 - (h >> 1);
    const int yoff = (h & 1) * 64;

    // ---- load Q tile (64 x 64 halfs) ----
    #pragma unroll
    for (int i = 0; i < 2; i++) {
        int f = tid + i * 256;           // 0..511 int4 units
        int r = f >> 3;
        int c = (f & 7) * 8;
        *(int4*)&Qh[r * 72 + c] =
            *(const int4*)&Hbuf[(size_t)(b * 2048 + q0 + r) * 2048 + qs * 128 + qoff + c];
    }
    __syncthreads();

    // ---- Q A-fragments (4 d-ktiles) in registers ----
    unsigned aq[4][4];
    #pragma unroll
    for (int kt = 0; kt < 4; kt++) {
        int col = kt * 16 + 2 * tq;
        aq[kt][0] = *(const unsigned*)&Qh[(wq + gid) * 72 + col];
        aq[kt][1] = *(const unsigned*)&Qh[(wq + gid + 8) * 72 + col];
        aq[kt][2] = *(const unsigned*)&Qh[(wq + gid) * 72 + col + 8];
        aq[kt][3] = *(const unsigned*)&Qh[(wq + gid + 8) * 72 + col + 8];
    }

    float m0v = -1e30f, m1v = -1e30f, l0v = 0.f, l1v = 0.f;
    float oa[4][4];
    #pragma unroll
    for (int nt = 0; nt < 4; nt++)
        #pragma unroll
        for (int c = 0; c < 4; c++) oa[nt][c] = 0.f;

    const int ntiles = blockIdx.x + 1;   // causal
    for (int it = 0; it < ntiles; it++) {
        const int k0 = it * 64;
        __syncthreads();   // prior tile's smem reads done

        // ---- fill K (key-major) ----
        #pragma unroll
        for (int i = 0; i < 2; i++) {
            int f = tid + i * 256;
            int r = f >> 3;
            int c = (f & 7) * 8;
            *(int4*)&Kh[r * 72 + c] =
                *(const int4*)&Hbuf[(size_t)(b * 2048 + k0 + r) * 2048 + kvs * 128 + c];
        }
        // ---- fill V transposed: Vt[d][j] ----
        #pragma unroll
        for (int i = 0; i < 8; i++) {
            int f  = tid + i * 256;      // 0..2047 half2 units
            int r  = f >> 5;             // key row 0..63
            int c2 = f & 31;             // d pair 0..31
            half2 v = *(const half2*)&Hbuf[(size_t)(b * 2048 + k0 + r) * 2048 + kvs * 128 + 64 + c2 * 2];
            Vt[(2 * c2 + 0) * 72 + r] = __low2half(v);
            Vt[(2 * c2 + 1) * 72 + r] = __high2half(v);
        }
        __syncthreads();

        // ---- score S = Q K^T (warp: 16q x 32k) ----
        float sacc[4][4];
        #pragma unroll
        for (int nt = 0; nt < 4; nt++)
            #pragma unroll
            for (int c = 0; c < 4; c++) sacc[nt][c] = 0.f;

        #pragma unroll
        for (int kt = 0; kt < 4; kt++) {
            #pragma unroll
            for (int nt = 0; nt < 4; nt++) {
                int krow = (wk + nt * 8 + gid) * 72 + kt * 16 + 2 * tq;
                unsigned bk0 = *(const unsigned*)&Kh[krow];
                unsigned bk1 = *(const unsigned*)&Kh[krow + 8];
                mma16816(sacc[nt], aq[kt], bk0, bk1);
            }
        }

        // ---- causal mask (diagonal tile only) ----
        if (k0 == q0) {
            #pragma unroll
            for (int nt = 0; nt < 4; nt++)
                #pragma unroll
                for (int c = 0; c < 4; c++) {
                    int col = wk + nt * 8 + 2 * tq + (c & 1);
                    int row = wq + gid + ((c >> 1) * 8);
                    if (col > row) sacc[nt][c] = -1e30f;
                }
        }

        // ---- row max (warp slice) ----
        float tm0 = -1e30f, tm1 = -1e30f;
        #pragma unroll
        for (int nt = 0; nt < 4; nt++) {
            tm0 = fmaxf(tm0, fmaxf(sacc[nt][0], sacc[nt][1]));
            tm1 = fmaxf(tm1, fmaxf(sacc[nt][2], sacc[nt][3]));
        }
        tm0 = fmaxf(tm0, __shfl_xor_sync(~0u, tm0, 1));
        tm0 = fmaxf(tm0, __shfl_xor_sync(~0u, tm0, 2));
        tm1 = fmaxf(tm1, __shfl_xor_sync(~0u, tm1, 1));
        tm1 = fmaxf(tm1, __shfl_xor_sync(~0u, tm1, 2));
        if (tq == 0) {
            redm[wc][wq + gid]     = tm0;
            redm[wc][wq + gid + 8] = tm1;
        }
        __syncthreads();
        float mn0 = fmaxf(m0v, fmaxf(redm[0][wq + gid],     redm[1][wq + gid]));
        float mn1 = fmaxf(m1v, fmaxf(redm[0][wq + gid + 8], redm[1][wq + gid + 8]));
        float alpha0 = __expf(m0v - mn0);
        float alpha1 = __expf(m1v - mn1);
        m0v = mn0; m1v = mn1;

        // ---- exp + row sum + P store ----
        float ts0 = 0.f, ts1 = 0.f;
        #pragma unroll
        for (int nt = 0; nt < 4; nt++) {
            sacc[nt][0] = __expf(sacc[nt][0] - mn0);
            sacc[nt][1] = __expf(sacc[nt][1] - mn0);
            sacc[nt][2] = __expf(sacc[nt][2] - mn1);
            sacc[nt][3] = __expf(sacc[nt][3] - mn1);
            ts0 += sacc[nt][0] + sacc[nt][1];
            ts1 += sacc[nt][2] + sacc[nt][3];
            int col = wk + nt * 8 + 2 * tq;
            *(half2*)&Ph[(wq + gid) * 72 + col]     = __floats2half2_rn(sacc[nt][0], sacc[nt][1]);
            *(half2*)&Ph[(wq + gid + 8) * 72 + col] = __floats2half2_rn(sacc[nt][2], sacc[nt][3]);
        }
        ts0 += __shfl_xor_sync(~0u, ts0, 1);
        ts0 += __shfl_xor_sync(~0u, ts0, 2);
        ts1 += __shfl_xor_sync(~0u, ts1, 1);
        ts1 += __shfl_xor_sync(~0u, ts1, 2);
        if (tq == 0) {
            reds[wc][wq + gid]     = ts0;
            reds[wc][wq + gid + 8] = ts1;
        }

        // ---- rescale O ----
        #pragma unroll
        for (int nt = 0; nt < 4; nt++) {
            oa[nt][0] *= alpha0;
            oa[nt][1] *= alpha0;
            oa[nt][2] *= alpha1;
            oa[nt][3] *= alpha1;
        }
        __syncthreads();   // reds + Ph visible
        l0v = l0v * alpha0 + reds[0][wq + gid]     + reds[1][wq + gid];
        l1v = l1v * alpha1 + reds[0][wq + gid + 8] + reds[1][wq + gid + 8];

        // ---- O += P V (warp: 16q x 32d) ----
        #pragma unroll
        for (int jt = 0; jt < 4; jt++) {
            int col = jt * 16 + 2 * tq;
            unsigned ap[4];
            ap[0] = *(const unsigned*)&Ph[(wq + gid) * 72 + col];
            ap[1] = *(const unsigned*)&Ph[(wq + gid + 8) * 72 + col];
            ap[2] = *(const unsigned*)&Ph[(wq + gid) * 72 + col + 8];
            ap[3] = *(const unsigned*)&Ph[(wq + gid + 8) * 72 + col + 8];
            #pragma unroll
            for (int nt = 0; nt < 4; nt++) {
                int vrow = (wk + nt * 8 + gid) * 72 + col;
                unsigned bv0 = *(const unsigned*)&Vt[vrow];
                unsigned bv1 = *(const unsigned*)&Vt[vrow + 8];
                mma16816(oa[nt], ap, bv0, bv1);
            }
        }
    }

    // ---- epilogue: normalize, fp16, write y ----
    float inv0 = 1.0f / l0v;
    float inv1 = 1.0f / l1v;
    const size_t row0 = (size_t)(b * 2048 + q0 + wq + gid);
    const size_t row1 = row0 + 8;
    #pragma unroll
    for (int nt = 0; nt < 4; nt++) {
        int col = wk + nt * 8 + 2 * tq;
        *(half2*)&Hbuf[row0 * 2048 + ys * 128 + yoff + col] =
            __floats2half2_rn(oa[nt][0] * inv0, oa[nt][1] * inv0);
        *(half2*)&Hbuf[row1 * 2048 + ys * 128 + yoff + col] =
            __floats2half2_rn(oa[nt][2] * inv1, oa[nt][3] * inv1);
    }
}

// ---------------------------------------------------------------------------
// In-place projection: block handles 32 rows. Gathers its rows' y (fp16, from
// the strip map) into smem, syncs, then overwrites those rows with fp32
// y @ W_proj + b_proj. Read set == own write set -> race-free.
// Dynamic smem: 64 KB y + 8 KB W tile = 72 KB.
// ---------------------------------------------------------------------------
__global__ __launch_bounds__(256) void proj_kernel(
    const float* __restrict__ Wp, const float* __restrict__ bp,
    float* __restrict__ out)
{
    extern __shared__ char smem_raw[];
    half*  ysm = (half*)smem_raw;                       // [32][1024]
    float* Wt  = (float*)(smem_raw + 32 * 1024 * 2);    // [16][128]

    const half* Hbuf = (const half*)out;
    const int tid = threadIdx.x;
    const int tx  = tid & 31;
    const int ty  = tid >> 5;
    const int m0  = blockIdx.x * 32;

    // Gather y rows (all 16 heads; head h at strip 15-(h>>1), half h&1)
    #pragma unroll
    for (int i = 0; i < 64; i++) {
        int f  = tid + i * 256;        // 0..16383 half2 items
        int r  = f >> 9;
        int c2 = f & 511;
        int hh = c2 >> 5;
        int d2 = c2 & 31;
        int ys = 15 - (hh >> 1);
        int yh = hh & 1;
        half2 v = *(const half2*)&Hbuf[(size_t)(m0 + r) * 2048 + ys * 128 + yh * 64 + d2 * 2];
        *(half2*)&ysm[r * 1024 + c2 * 2] = v;
    }
    __syncthreads();

    for (int nt = 0; nt < 8; nt++) {
        float acc[4][4];
        #pragma unroll
        for (int r = 0; r < 4; r++)
            #pragma unroll
            for (int c = 0; c < 4; c++) acc[r][c] = 0.f;

        for (int k0 = 0; k0 < C_; k0 += 16) {
            __syncthreads();
            #pragma unroll
            for (int i = 0; i < 2; i++) {
                int f   = tid + i * 256;
                int row = f >> 5;
                int c4  = (f & 31) * 4;
                *(float4*)&Wt[row * 128 + c4] =
                    *(const float4*)&Wp[(size_t)(k0 + row) * C_ + nt * 128 + c4];
            }
            __syncthreads();

            #pragma unroll
            for (int k = 0; k < 16; k++) {
                float4 b4 = *(float4*)&Wt[k * 128 + tx * 4];
                float a[4];
                #pragma unroll
                for (int r = 0; r < 4; r++)
                    a[r] = __half2float(ysm[(ty * 4 + r) * 1024 + k0 + k]);
                #pragma unroll
                for (int r = 0; r < 4; r++) {
                    acc[r][0] += a[r] * b4.x;
                    acc[r][1] += a[r] * b4.y;
                    acc[r][2] += a[r] * b4.z;
                    acc[r][3] += a[r] * b4.w;
                }
            }
        }

        float4 bb = *(const float4*)&bp[nt * 128 + tx * 4];
        #pragma unroll
        for (int r = 0; r < 4; r++) {
            float4 outv;
            outv.x = acc[r][0] + bb.x;
            outv.y = acc[r][1] + bb.y;
            outv.z = acc[r][2] + bb.z;
            outv.w = acc[r][3] + bb.w;
            *(float4*)&out[(size_t)(m0 + ty * 4 + r) * C_ + nt * 128 + tx * 4] = outv;
        }
    }
}

// ---------------------------------------------------------------------------
extern "C" void kernel_launch(void* const* d_in, const int* in_sizes, int n_in,
                              void* d_out, int out_size)
{
    const float* x      = (const float*)d_in[0];
    const float* W_attn = (const float*)d_in[1];
    const float* b_attn = (const float*)d_in[2];
    const float* W_proj = (const float*)d_in[3];
    const float* b_proj = (const float*)d_in[4];
    float* out  = (float*)d_out;
    half*  Hbuf = (half*)d_out;

    const int hbase_w[3] = {0, 6, 12};
    const int nh_w[3]    = {6, 6, 4};

    for (int wv = 0; wv < 3; wv++) {
        const int hbase = hbase_w[wv];
        const int nh    = nh_w[wv];
        // K,V,Q fp16 for this wave's heads
        kvq_kernel<<<dim3(nh * 3, M_ / 128), 256>>>(x, W_attn, b_attn, Hbuf, hbase);
        // tensor-core causal flash; y -> persistent strips
        flash_mma<<<dim3(T_ / 64, B_, nh), 256>>>(Hbuf, hbase);
    }

    // In-place projection (72 KB dynamic smem)
    cudaFuncSetAttribute(proj_kernel, cudaFuncAttributeMaxDynamicSharedMemorySize, 73728);
    proj_kernel<<<128, 256, 73728>>>(W_proj, b_proj, out);
}

// round 13
// speedup vs baseline: 2.9940x; 1.5402x over previous
#include <cuda_runtime.h>
#include <cuda_fp16.h>
#include <math.h>

// Problem constants
#define B_  2
#define T_  2048
#define C_  1024
#define H_  16
#define D_  64
#define M_  (B_*T_)          // 4096
#define N3_ (3*C_)           // 3072

// NO __device__ globals, NO static initializers (R2-R10: any module data
// segment triggers a 128 MiB driver slab inside the checkpointed run).
// All scratch lives in d_out (16 MiB = 4096 rows x 2048 halfs), in "strips":
// strip s of row m = halfs [m*2048 + s*128, +128).
//
// 3 head-waves {6,6,4}. Per wave (local head hl, global h = hbase+hl):
//   K fp16 -> strip hl, off 0; V -> strip hl, off 64
//   Q fp16 -> strip 6+(hl>>1), off (hl&1)*64
//   y fp16 -> strip 15-(h>>1), off (h&1)*64 (persistent)
// Strip 8 is Q-only in waves 0-1 and y-only in wave 2 -> no collisions.

// ---------------------------------------------------------------------------
// mma helper: m16n8k16 row.col f32 = f16 x f16 + f32
// ---------------------------------------------------------------------------
__device__ __forceinline__ void mma16816(
    float c[4], const unsigned a[4], unsigned b0, unsigned b1)
{
    asm volatile(
        "mma.sync.aligned.m16n8k16.row.col.f32.f16.f16.f32 "
        "{%0,%1,%2,%3}, {%4,%5,%6,%7}, {%8,%9}, {%0,%1,%2,%3};"
        : "+f"(c[0]), "+f"(c[1]), "+f"(c[2]), "+f"(c[3])
        : "r"(a[0]), "r"(a[1]), "r"(a[2]), "r"(a[3]), "r"(b0), "r"(b1));
}

// ---------------------------------------------------------------------------
// kvq (tensor-core): fused QKV GEMM + bias (+ RMS-norm + rotary for K/Q) for
// one wave. Block 128m x 64n, 8 warps (4m x 2n), K in chunks of 64.
// x tile fp32->fp16 in Xs[m][k] (stride 66: conflict-free), W transposed into
// Ws[n][k] stride 66 (B fragment layout identical to flash's Kh). Epilogue:
// fragments -> fp32 Es (overlay), then the proven shuffle RMS+rope epilogue.
// Dynamic smem: max(Xs+Ws, Es) = 34816 B.
// ---------------------------------------------------------------------------
__global__ __launch_bounds__(256) void kvq_kernel(
    const float* __restrict__ x, const float* __restrict__ Wa,
    const float* __restrict__ ba, half* __restrict__ Hbuf, int hbase)
{
    extern __shared__ char dsm[];
    half*  Xs = (half*)dsm;             // [128][66]
    half*  Ws = Xs + 128 * 66;          // [64][66]  (Ws[n][k])
    float* Es = (float*)dsm;            // [128][68] overlay (epilogue)

    const int tid  = threadIdx.x;
    const int lane = tid & 31;
    const int w    = tid >> 5;
    const int gid  = lane >> 2;
    const int tq   = lane & 3;
    const int wm   = (w >> 1) * 32;     // warp m offset
    const int wn   = (w & 1) * 32;      // warp n offset

    const int m0   = blockIdx.y * 128;
    const int hl   = blockIdx.x / 3;
    const int kind = blockIdx.x % 3;              // 0=K, 1=V, 2=Q
    const int h    = hbase + hl;
    const int n0   = (kind == 0 ? C_ : (kind == 1 ? 2 * C_ : 0)) + h * 64;
    const int s    = (kind == 2) ? (6 + (hl >> 1)) : hl;
    const int off  = (kind == 2) ? ((hl & 1) * 64) : (kind == 1 ? 64 : 0);

    float acc[2][4][4];
    #pragma unroll
    for (int mt = 0; mt < 2; mt++)
        #pragma unroll
        for (int nt = 0; nt < 4; nt++)
            #pragma unroll
            for (int c = 0; c < 4; c++) acc[mt][nt][c] = 0.f;

    for (int k0 = 0; k0 < C_; k0 += 64) {
        __syncthreads();   // prior chunk's mma reads done
        // Xs: x[128][64] fp32 -> fp16
        #pragma unroll
        for (int i = 0; i < 8; i++) {
            int f  = tid + i * 256;          // float4 items
            int m  = f >> 4;
            int kc = (f & 15) * 4;
            float4 a4 = *(const float4*)&x[(size_t)(m0 + m) * C_ + k0 + kc];
            *(half2*)&Xs[m * 66 + kc]     = __floats2half2_rn(a4.x, a4.y);
            *(half2*)&Xs[m * 66 + kc + 2] = __floats2half2_rn(a4.z, a4.w);
        }
        // Ws: W[64k][64n] -> Ws[n][k] fp16 (transposed)
        #pragma unroll
        for (int i = 0; i < 8; i++) {
            int f  = tid + i * 256;          // float2 items
            int n2 = f & 31;                 // n pair
            int k  = f >> 5;
            float2 wv = *(const float2*)&Wa[(size_t)(k0 + k) * N3_ + n0 + 2 * n2];
            Ws[(2 * n2 + 0) * 66 + k] = __float2half_rn(wv.x);
            Ws[(2 * n2 + 1) * 66 + k] = __float2half_rn(wv.y);
        }
        __syncthreads();

        #pragma unroll
        for (int kt = 0; kt < 4; kt++) {
            unsigned af[2][4];
            #pragma unroll
            for (int mt = 0; mt < 2; mt++) {
                int row = wm + mt * 16 + gid;
                int col = kt * 16 + 2 * tq;
                af[mt][0] = *(const unsigned*)&Xs[row * 66 + col];
                af[mt][1] = *(const unsigned*)&Xs[(row + 8) * 66 + col];
                af[mt][2] = *(const unsigned*)&Xs[row * 66 + col + 8];
                af[mt][3] = *(const unsigned*)&Xs[(row + 8) * 66 + col + 8];
            }
            #pragma unroll
            for (int nt = 0; nt < 4; nt++) {
                int nrow = (wn + nt * 8 + gid) * 66 + kt * 16 + 2 * tq;
                unsigned b0 = *(const unsigned*)&Ws[nrow];
                unsigned b1 = *(const unsigned*)&Ws[nrow + 8];
                mma16816(acc[0][nt], af[0], b0, b1);
                mma16816(acc[1][nt], af[1], b0, b1);
            }
        }
    }

    __syncthreads();   // mainloop smem dead
    // dump fragments to Es[m][n] (stride 68)
    #pragma unroll
    for (int mt = 0; mt < 2; mt++)
        #pragma unroll
        for (int nt = 0; nt < 4; nt++) {
            int r0 = wm + mt * 16 + gid;
            int c  = wn + nt * 8 + 2 * tq;
            *(float2*)&Es[r0 * 68 + c]       = make_float2(acc[mt][nt][0], acc[mt][nt][1]);
            *(float2*)&Es[(r0 + 8) * 68 + c] = make_float2(acc[mt][nt][2], acc[mt][nt][3]);
        }
    __syncthreads();

    // ---- proven epilogue (per-row shuffle RMS + rotary), reading Es ----
    const int tx = tid & 15;
    const int ty = tid >> 4;

    float4 bv = *(const float4*)&ba[n0 + tx * 4];
    const float bias_c[4] = {bv.x, bv.y, bv.z, bv.w};

    if (kind == 1) {
        // V: plain fp16 store
        #pragma unroll
        for (int r = 0; r < 8; r++) {
            float4 v4 = *(float4*)&Es[(ty * 8 + r) * 68 + tx * 4];
            const size_t idx = (size_t)(m0 + ty * 8 + r) * 2048 + s * 128 + off + tx * 4;
            *(half2*)&Hbuf[idx]     = __floats2half2_rn(v4.x + bias_c[0], v4.y + bias_c[1]);
            *(half2*)&Hbuf[idx + 2] = __floats2half2_rn(v4.z + bias_c[2], v4.w + bias_c[3]);
        }
        return;
    }

    // K/Q: RMS-norm + rotary (angle = h * 10000^(-j/32), j = (tx&7)*4 + c)
    float csv[4], snv[4];
    #pragma unroll
    for (int c = 0; c < 4; c++) {
        int j = ((tx & 7) * 4) + c;
        float ang = (float)h * __expf(-(float)j * 0.28782313662425572f);
        __sincosf(ang, &snv[c], &csv[c]);
    }
    const float scale = (kind == 2) ? 0.125f : 1.0f;
    const bool lo_half = (tx < 8);

    #pragma unroll
    for (int r = 0; r < 8; r++) {
        float4 v4 = *(float4*)&Es[(ty * 8 + r) * 68 + tx * 4];
        float v0 = v4.x + bias_c[0];
        float v1 = v4.y + bias_c[1];
        float v2 = v4.z + bias_c[2];
        float v3 = v4.w + bias_c[3];

        float ss = v0 * v0 + v1 * v1 + v2 * v2 + v3 * v3;
        ss += __shfl_xor_sync(~0u, ss, 1);
        ss += __shfl_xor_sync(~0u, ss, 2);
        ss += __shfl_xor_sync(~0u, ss, 4);
        ss += __shfl_xor_sync(~0u, ss, 8);
        float sc = rsqrtf(ss * (1.0f / 64.0f) + 1.1920929e-07f);
        v0 *= sc; v1 *= sc; v2 *= sc; v3 *= sc;

        float p0 = __shfl_xor_sync(~0u, v0, 8);
        float p1 = __shfl_xor_sync(~0u, v1, 8);
        float p2 = __shfl_xor_sync(~0u, v2, 8);
        float p3 = __shfl_xor_sync(~0u, v3, 8);

        float o0, o1, o2, o3;
        if (lo_half) {
            o0 = v0 * csv[0] + p0 * snv[0];
            o1 = v1 * csv[1] + p1 * snv[1];
            o2 = v2 * csv[2] + p2 * snv[2];
            o3 = v3 * csv[3] + p3 * snv[3];
        } else {
            o0 = v0 * csv[0] - p0 * snv[0];
            o1 = v1 * csv[1] - p1 * snv[1];
            o2 = v2 * csv[2] - p2 * snv[2];
            o3 = v3 * csv[3] - p3 * snv[3];
        }

        const size_t idx = (size_t)(m0 + ty * 8 + r) * 2048 + s * 128 + off + tx * 4;
        *(half2*)&Hbuf[idx]     = __floats2half2_rn(o0 * scale, o1 * scale);
        *(half2*)&Hbuf[idx + 2] = __floats2half2_rn(o2 * scale, o3 * scale);
    }
}

// ---------------------------------------------------------------------------
// Tensor-core causal flash for one wave (UNCHANGED from R12 — verified).
// ---------------------------------------------------------------------------
__global__ __launch_bounds__(256) void flash_mma(half* __restrict__ Hbuf, int hbase)
{
    __shared__ half Qh[64 * 72];
    __shared__ half Kh[64 * 72];
    __shared__ half Vt[64 * 72];
    __shared__ half Ph[64 * 72];
    __shared__ float redm[2][64];
    __shared__ float reds[2][64];

    const int tid  = threadIdx.x;
    const int lane = tid & 31;
    const int w    = tid >> 5;
    const int gid  = lane >> 2;
    const int tq   = lane & 3;
    const int wq   = (w >> 1) * 16;
    const int wk   = (w & 1) * 32;
    const int wc   = w & 1;

    const int hl = blockIdx.z;
    const int h  = hbase + hl;
    const int b  = blockIdx.y;
    const int q0 = blockIdx.x * 64;
    const int kvs = hl;
    const int qs  = 6 + (hl >> 1);
    const int qoff = (hl & 1) * 64;
    const int ys  = 15 - (h >> 1);
    const int yoff = (h & 1) * 64;

    #pragma unroll
    for (int i = 0; i < 2; i++) {
        int f = tid + i * 256;
        int r = f >> 3;
        int c = (f & 7) * 8;
        *(int4*)&Qh[r * 72 + c] =
            *(const int4*)&Hbuf[(size_t)(b * 2048 + q0 + r) * 2048 + qs * 128 + qoff + c];
    }
    __syncthreads();

    unsigned aq[4][4];
    #pragma unroll
    for (int kt = 0; kt < 4; kt++) {
        int col = kt * 16 + 2 * tq;
        aq[kt][0] = *(const unsigned*)&Qh[(wq + gid) * 72 + col];
        aq[kt][1] = *(const unsigned*)&Qh[(wq + gid + 8) * 72 + col];
        aq[kt][2] = *(const unsigned*)&Qh[(wq + gid) * 72 + col + 8];
        aq[kt][3] = *(const unsigned*)&Qh[(wq + gid + 8) * 72 + col + 8];
    }

    float m0v = -1e30f, m1v = -1e30f, l0v = 0.f, l1v = 0.f;
    float oa[4][4];
    #pragma unroll
    for (int nt = 0; nt < 4; nt++)
        #pragma unroll
        for (int c = 0; c < 4; c++) oa[nt][c] = 0.f;

    const int ntiles = blockIdx.x + 1;
    for (int it = 0; it < ntiles; it++) {
        const int k0 = it * 64;
        __syncthreads();

        #pragma unroll
        for (int i = 0; i < 2; i++) {
            int f = tid + i * 256;
            int r = f >> 3;
            int c = (f & 7) * 8;
            *(int4*)&Kh[r * 72 + c] =
                *(const int4*)&Hbuf[(size_t)(b * 2048 + k0 + r) * 2048 + kvs * 128 + c];
        }
        #pragma unroll
        for (int i = 0; i < 8; i++) {
            int f  = tid + i * 256;
            int r  = f >> 5;
            int c2 = f & 31;
            half2 v = *(const half2*)&Hbuf[(size_t)(b * 2048 + k0 + r) * 2048 + kvs * 128 + 64 + c2 * 2];
            Vt[(2 * c2 + 0) * 72 + r] = __low2half(v);
            Vt[(2 * c2 + 1) * 72 + r] = __high2half(v);
        }
        __syncthreads();

        float sacc[4][4];
        #pragma unroll
        for (int nt = 0; nt < 4; nt++)
            #pragma unroll
            for (int c = 0; c < 4; c++) sacc[nt][c] = 0.f;

        #pragma unroll
        for (int kt = 0; kt < 4; kt++) {
            #pragma unroll
            for (int nt = 0; nt < 4; nt++) {
                int krow = (wk + nt * 8 + gid) * 72 + kt * 16 + 2 * tq;
                unsigned bk0 = *(const unsigned*)&Kh[krow];
                unsigned bk1 = *(const unsigned*)&Kh[krow + 8];
                mma16816(sacc[nt], aq[kt], bk0, bk1);
            }
        }

        if (k0 == q0) {
            #pragma unroll
            for (int nt = 0; nt < 4; nt++)
                #pragma unroll
                for (int c = 0; c < 4; c++) {
                    int col = wk + nt * 8 + 2 * tq + (c & 1);
                    int row = wq + gid + ((c >> 1) * 8);
                    if (col > row) sacc[nt][c] = -1e30f;
                }
        }

        float tm0 = -1e30f, tm1 = -1e30f;
        #pragma unroll
        for (int nt = 0; nt < 4; nt++) {
            tm0 = fmaxf(tm0, fmaxf(sacc[nt][0], sacc[nt][1]));
            tm1 = fmaxf(tm1, fmaxf(sacc[nt][2], sacc[nt][3]));
        }
        tm0 = fmaxf(tm0, __shfl_xor_sync(~0u, tm0, 1));
        tm0 = fmaxf(tm0, __shfl_xor_sync(~0u, tm0, 2));
        tm1 = fmaxf(tm1, __shfl_xor_sync(~0u, tm1, 1));
        tm1 = fmaxf(tm1, __shfl_xor_sync(~0u, tm1, 2));
        if (tq == 0) {
            redm[wc][wq + gid]     = tm0;
            redm[wc][wq + gid + 8] = tm1;
        }
        __syncthreads();
        float mn0 = fmaxf(m0v, fmaxf(redm[0][wq + gid],     redm[1][wq + gid]));
        float mn1 = fmaxf(m1v, fmaxf(redm[0][wq + gid + 8], redm[1][wq + gid + 8]));
        float alpha0 = __expf(m0v - mn0);
        float alpha1 = __expf(m1v - mn1);
        m0v = mn0; m1v = mn1;

        float ts0 = 0.f, ts1 = 0.f;
        #pragma unroll
        for (int nt = 0; nt < 4; nt++) {
            sacc[nt][0] = __expf(sacc[nt][0] - mn0);
            sacc[nt][1] = __expf(sacc[nt][1] - mn0);
            sacc[nt][2] = __expf(sacc[nt][2] - mn1);
            sacc[nt][3] = __expf(sacc[nt][3] - mn1);
            ts0 += sacc[nt][0] + sacc[nt][1];
            ts1 += sacc[nt][2] + sacc[nt][3];
            int col = wk + nt * 8 + 2 * tq;
            *(half2*)&Ph[(wq + gid) * 72 + col]     = __floats2half2_rn(sacc[nt][0], sacc[nt][1]);
            *(half2*)&Ph[(wq + gid + 8) * 72 + col] = __floats2half2_rn(sacc[nt][2], sacc[nt][3]);
        }
        ts0 += __shfl_xor_sync(~0u, ts0, 1);
        ts0 += __shfl_xor_sync(~0u, ts0, 2);
        ts1 += __shfl_xor_sync(~0u, ts1, 1);
        ts1 += __shfl_xor_sync(~0u, ts1, 2);
        if (tq == 0) {
            reds[wc][wq + gid]     = ts0;
            reds[wc][wq + gid + 8] = ts1;
        }

        #pragma unroll
        for (int nt = 0; nt < 4; nt++) {
            oa[nt][0] *= alpha0;
            oa[nt][1] *= alpha0;
            oa[nt][2] *= alpha1;
            oa[nt][3] *= alpha1;
        }
        __syncthreads();
        l0v = l0v * alpha0 + reds[0][wq + gid]     + reds[1][wq + gid];
        l1v = l1v * alpha1 + reds[0][wq + gid + 8] + reds[1][wq + gid + 8];

        #pragma unroll
        for (int jt = 0; jt < 4; jt++) {
            int col = jt * 16 + 2 * tq;
            unsigned ap[4];
            ap[0] = *(const unsigned*)&Ph[(wq + gid) * 72 + col];
            ap[1] = *(const unsigned*)&Ph[(wq + gid + 8) * 72 + col];
            ap[2] = *(const unsigned*)&Ph[(wq + gid) * 72 + col + 8];
            ap[3] = *(const unsigned*)&Ph[(wq + gid + 8) * 72 + col + 8];
            #pragma unroll
            for (int nt = 0; nt < 4; nt++) {
                int vrow = (wk + nt * 8 + gid) * 72 + col;
                unsigned bv0 = *(const unsigned*)&Vt[vrow];
                unsigned bv1 = *(const unsigned*)&Vt[vrow + 8];
                mma16816(oa[nt], ap, bv0, bv1);
            }
        }
    }

    float inv0 = 1.0f / l0v;
    float inv1 = 1.0f / l1v;
    const size_t row0 = (size_t)(b * 2048 + q0 + wq + gid);
    const size_t row1 = row0 + 8;
    #pragma unroll
    for (int nt = 0; nt < 4; nt++) {
        int col = wk + nt * 8 + 2 * tq;
        *(half2*)&Hbuf[row0 * 2048 + ys * 128 + yoff + col] =
            __floats2half2_rn(oa[nt][0] * inv0, oa[nt][1] * inv0);
        *(half2*)&Hbuf[row1 * 2048 + ys * 128 + yoff + col] =
            __floats2half2_rn(oa[nt][2] * inv1, oa[nt][3] * inv1);
    }
}

// ---------------------------------------------------------------------------
// proj (tensor-core, in-place): block = 32 rows x full 1024 cols (8 n-tiles
// of 128). Gathers its y rows (fp16, strip map) into ysm (stride 1032:
// conflict-free A-frags), then per n-tile: W_proj fp32->fp16 transposed tiles
// Ws[n][k] (stride 66), mma accumulate fp32, write fp32 + bias to out.
// Read set == own write set -> race-free. Dyn smem 82944 B.
// ---------------------------------------------------------------------------
__global__ __launch_bounds__(256) void proj_kernel(
    const float* __restrict__ Wp, const float* __restrict__ bp,
    float* __restrict__ out)
{
    extern __shared__ char dsm[];
    half* ysm = (half*)dsm;             // [32][1032]
    half* Ws  = ysm + 32 * 1032;        // [128][66]

    const half* Hbuf = (const half*)out;
    const int tid  = threadIdx.x;
    const int lane = tid & 31;
    const int w    = tid >> 5;
    const int gid  = lane >> 2;
    const int tq   = lane & 3;
    const int wm   = (w >> 2) * 16;     // warp m offset (0/16)
    const int wn   = (w & 3) * 32;      // warp n offset (0..96)
    const int m0   = blockIdx.x * 32;

    // Gather y rows (head h at strip 15-(h>>1), half h&1)
    #pragma unroll
    for (int i = 0; i < 64; i++) {
        int f  = tid + i * 256;        // half2 items
        int r  = f >> 9;
        int c2 = f & 511;
        int hh = c2 >> 5;
        int d2 = c2 & 31;
        int ys = 15 - (hh >> 1);
        int yh = hh & 1;
        half2 v = *(const half2*)&Hbuf[(size_t)(m0 + r) * 2048 + ys * 128 + yh * 64 + d2 * 2];
        *(half2*)&ysm[r * 1032 + c2 * 2] = v;
    }
    __syncthreads();

    for (int ntile = 0; ntile < 8; ntile++) {
        float acc[4][4];
        #pragma unroll
        for (int nt = 0; nt < 4; nt++)
            #pragma unroll
            for (int c = 0; c < 4; c++) acc[nt][c] = 0.f;

        for (int k0 = 0; k0 < C_; k0 += 64) {
            __syncthreads();   // prior Ws reads done
            // Ws: Wp[64k][128n] -> Ws[n][k] fp16 (transposed)
            #pragma unroll
            for (int i = 0; i < 16; i++) {
                int f  = tid + i * 256;      // float2 items
                int n2 = f & 63;
                int k  = f >> 6;
                float2 wv = *(const float2*)&Wp[(size_t)(k0 + k) * C_ + ntile * 128 + 2 * n2];
                Ws[(2 * n2 + 0) * 66 + k] = __float2half_rn(wv.x);
                Ws[(2 * n2 + 1) * 66 + k] = __float2half_rn(wv.y);
            }
            __syncthreads();

            #pragma unroll
            for (int kt = 0; kt < 4; kt++) {
                int col = k0 + kt * 16 + 2 * tq;
                unsigned af[4];
                af[0] = *(const unsigned*)&ysm[(wm + gid) * 1032 + col];
                af[1] = *(const unsigned*)&ysm[(wm + gid + 8) * 1032 + col];
                af[2] = *(const unsigned*)&ysm[(wm + gid) * 1032 + col + 8];
                af[3] = *(const unsigned*)&ysm[(wm + gid + 8) * 1032 + col + 8];
                #pragma unroll
                for (int nt = 0; nt < 4; nt++) {
                    int nrow = (wn + nt * 8 + gid) * 66 + kt * 16 + 2 * tq;
                    unsigned b0 = *(const unsigned*)&Ws[nrow];
                    unsigned b1 = *(const unsigned*)&Ws[nrow + 8];
                    mma16816(acc[nt], af, b0, b1);
                }
            }
        }

        // write out (+bias)
        #pragma unroll
        for (int nt = 0; nt < 4; nt++) {
            int col = ntile * 128 + wn + nt * 8 + 2 * tq;
            float2 bb = *(const float2*)&bp[col];
            size_t r0 = (size_t)(m0 + wm + gid);
            *(float2*)&out[r0 * C_ + col] =
                make_float2(acc[nt][0] + bb.x, acc[nt][1] + bb.y);
            *(float2*)&out[(r0 + 8) * C_ + col] =
                make_float2(acc[nt][2] + bb.x, acc[nt][3] + bb.y);
        }
    }
}

// ---------------------------------------------------------------------------
extern "C" void kernel_launch(void* const* d_in, const int* in_sizes, int n_in,
                              void* d_out, int out_size)
{
    const float* x      = (const float*)d_in[0];
    const float* W_attn = (const float*)d_in[1];
    const float* b_attn = (const float*)d_in[2];
    const float* W_proj = (const float*)d_in[3];
    const float* b_proj = (const float*)d_in[4];
    float* out  = (float*)d_out;
    half*  Hbuf = (half*)d_out;

    const int hbase_w[3] = {0, 6, 12};
    const int nh_w[3]    = {6, 6, 4};

    const int kvq_smem  = 128 * 68 * 4;                    // 34816 (Es overlay max)
    const int proj_smem = 32 * 1032 * 2 + 128 * 66 * 2;    // 82944

    cudaFuncSetAttribute(proj_kernel, cudaFuncAttributeMaxDynamicSharedMemorySize, proj_smem);

    for (int wv = 0; wv < 3; wv++) {
        const int hbase = hbase_w[wv];
        const int nh    = nh_w[wv];
        kvq_kernel<<<dim3(nh * 3, M_ / 128), 256, kvq_smem>>>(x, W_attn, b_attn, Hbuf, hbase);
        flash_mma<<<dim3(T_ / 64, B_, nh), 256>>>(Hbuf, hbase);
    }

    proj_kernel<<<128, 256, proj_smem>>>(W_proj, b_proj, out);
}

// round 14
// speedup vs baseline: 3.1102x; 1.0388x over previous
#include <cuda_runtime.h>
#include <cuda_fp16.h>
#include <math.h>

// Problem constants
#define B_  2
#define T_  2048
#define C_  1024
#define H_  16
#define D_  64
#define M_  (B_*T_)          // 4096
#define N3_ (3*C_)           // 3072

// NO __device__ globals, NO static initializers (R2-R10: any module data
// segment triggers a 128 MiB driver slab inside the checkpointed run).
// All scratch lives in d_out (16 MiB = 4096 rows x 2048 halfs), in "strips":
// strip s of row m = halfs [m*2048 + s*128, +128).
//
// 2 head-waves of 8. Per wave (local head hl = h - hbase):
//   K fp16 -> strip hl, off 0;  V fp16 -> strip hl, off 64
//   Q fp16 -> strip 8+(h>>1), off (h&1)*64   (wave0: s8-11, wave1: s12-15)
//   y fp16 OVERWRITES Q in place (safe: Q[row r,h] is read only by the flash
//   block owning row r, which writes y[r,h] strictly after that read; other
//   blocks touch disjoint rows / the other 64-half of the strip).
// proj reads y at strip 8+(h>>1), half h&1, for all 16 heads.

// ---------------------------------------------------------------------------
// mma helper: m16n8k16 row.col f32 = f16 x f16 + f32
// ---------------------------------------------------------------------------
__device__ __forceinline__ void mma16816(
    float c[4], const unsigned a[4], unsigned b0, unsigned b1)
{
    asm volatile(
        "mma.sync.aligned.m16n8k16.row.col.f32.f16.f16.f32 "
        "{%0,%1,%2,%3}, {%4,%5,%6,%7}, {%8,%9}, {%0,%1,%2,%3};"
        : "+f"(c[0]), "+f"(c[1]), "+f"(c[2]), "+f"(c[3])
        : "r"(a[0]), "r"(a[1]), "r"(a[2]), "r"(a[3]), "r"(b0), "r"(b1));
}

// ---------------------------------------------------------------------------
// kvq (tensor-core): fused QKV GEMM + bias (+ RMS-norm + rotary for K/Q) for
// one wave of 8 heads. Block 128m x 64n, 8 warps (4m x 2n), K chunks of 64.
// bx = hl*3 + kind. Internals unchanged from R13 (verified).
// ---------------------------------------------------------------------------
__global__ __launch_bounds__(256) void kvq_kernel(
    const float* __restrict__ x, const float* __restrict__ Wa,
    const float* __restrict__ ba, half* __restrict__ Hbuf, int hbase)
{
    extern __shared__ char dsm[];
    half*  Xs = (half*)dsm;             // [128][66]
    half*  Ws = Xs + 128 * 66;          // [64][66]  (Ws[n][k])
    float* Es = (float*)dsm;            // [128][68] overlay (epilogue)

    const int tid  = threadIdx.x;
    const int lane = tid & 31;
    const int w    = tid >> 5;
    const int gid  = lane >> 2;
    const int tq   = lane & 3;
    const int wm   = (w >> 1) * 32;
    const int wn   = (w & 1) * 32;

    const int m0   = blockIdx.y * 128;
    const int hl   = blockIdx.x / 3;
    const int kind = blockIdx.x % 3;              // 0=K, 1=V, 2=Q
    const int h    = hbase + hl;
    const int n0   = (kind == 0 ? C_ : (kind == 1 ? 2 * C_ : 0)) + h * 64;
    const int s    = (kind == 2) ? (8 + (h >> 1)) : hl;
    const int off  = (kind == 2) ? ((h & 1) * 64) : (kind == 1 ? 64 : 0);

    float acc[2][4][4];
    #pragma unroll
    for (int mt = 0; mt < 2; mt++)
        #pragma unroll
        for (int nt = 0; nt < 4; nt++)
            #pragma unroll
            for (int c = 0; c < 4; c++) acc[mt][nt][c] = 0.f;

    for (int k0 = 0; k0 < C_; k0 += 64) {
        __syncthreads();
        #pragma unroll
        for (int i = 0; i < 8; i++) {
            int f  = tid + i * 256;
            int m  = f >> 4;
            int kc = (f & 15) * 4;
            float4 a4 = *(const float4*)&x[(size_t)(m0 + m) * C_ + k0 + kc];
            *(half2*)&Xs[m * 66 + kc]     = __floats2half2_rn(a4.x, a4.y);
            *(half2*)&Xs[m * 66 + kc + 2] = __floats2half2_rn(a4.z, a4.w);
        }
        #pragma unroll
        for (int i = 0; i < 8; i++) {
            int f  = tid + i * 256;
            int n2 = f & 31;
            int k  = f >> 5;
            float2 wv = *(const float2*)&Wa[(size_t)(k0 + k) * N3_ + n0 + 2 * n2];
            Ws[(2 * n2 + 0) * 66 + k] = __float2half_rn(wv.x);
            Ws[(2 * n2 + 1) * 66 + k] = __float2half_rn(wv.y);
        }
        __syncthreads();

        #pragma unroll
        for (int kt = 0; kt < 4; kt++) {
            unsigned af[2][4];
            #pragma unroll
            for (int mt = 0; mt < 2; mt++) {
                int row = wm + mt * 16 + gid;
                int col = kt * 16 + 2 * tq;
                af[mt][0] = *(const unsigned*)&Xs[row * 66 + col];
                af[mt][1] = *(const unsigned*)&Xs[(row + 8) * 66 + col];
                af[mt][2] = *(const unsigned*)&Xs[row * 66 + col + 8];
                af[mt][3] = *(const unsigned*)&Xs[(row + 8) * 66 + col + 8];
            }
            #pragma unroll
            for (int nt = 0; nt < 4; nt++) {
                int nrow = (wn + nt * 8 + gid) * 66 + kt * 16 + 2 * tq;
                unsigned b0 = *(const unsigned*)&Ws[nrow];
                unsigned b1 = *(const unsigned*)&Ws[nrow + 8];
                mma16816(acc[0][nt], af[0], b0, b1);
                mma16816(acc[1][nt], af[1], b0, b1);
            }
        }
    }

    __syncthreads();
    #pragma unroll
    for (int mt = 0; mt < 2; mt++)
        #pragma unroll
        for (int nt = 0; nt < 4; nt++) {
            int r0 = wm + mt * 16 + gid;
            int c  = wn + nt * 8 + 2 * tq;
            *(float2*)&Es[r0 * 68 + c]       = make_float2(acc[mt][nt][0], acc[mt][nt][1]);
            *(float2*)&Es[(r0 + 8) * 68 + c] = make_float2(acc[mt][nt][2], acc[mt][nt][3]);
        }
    __syncthreads();

    const int tx = tid & 15;
    const int ty = tid >> 4;

    float4 bv = *(const float4*)&ba[n0 + tx * 4];
    const float bias_c[4] = {bv.x, bv.y, bv.z, bv.w};

    if (kind == 1) {
        #pragma unroll
        for (int r = 0; r < 8; r++) {
            float4 v4 = *(float4*)&Es[(ty * 8 + r) * 68 + tx * 4];
            const size_t idx = (size_t)(m0 + ty * 8 + r) * 2048 + s * 128 + off + tx * 4;
            *(half2*)&Hbuf[idx]     = __floats2half2_rn(v4.x + bias_c[0], v4.y + bias_c[1]);
            *(half2*)&Hbuf[idx + 2] = __floats2half2_rn(v4.z + bias_c[2], v4.w + bias_c[3]);
        }
        return;
    }

    float csv[4], snv[4];
    #pragma unroll
    for (int c = 0; c < 4; c++) {
        int j = ((tx & 7) * 4) + c;
        float ang = (float)h * __expf(-(float)j * 0.28782313662425572f);
        __sincosf(ang, &snv[c], &csv[c]);
    }
    const float scale = (kind == 2) ? 0.125f : 1.0f;
    const bool lo_half = (tx < 8);

    #pragma unroll
    for (int r = 0; r < 8; r++) {
        float4 v4 = *(float4*)&Es[(ty * 8 + r) * 68 + tx * 4];
        float v0 = v4.x + bias_c[0];
        float v1 = v4.y + bias_c[1];
        float v2 = v4.z + bias_c[2];
        float v3 = v4.w + bias_c[3];

        float ss = v0 * v0 + v1 * v1 + v2 * v2 + v3 * v3;
        ss += __shfl_xor_sync(~0u, ss, 1);
        ss += __shfl_xor_sync(~0u, ss, 2);
        ss += __shfl_xor_sync(~0u, ss, 4);
        ss += __shfl_xor_sync(~0u, ss, 8);
        float sc = rsqrtf(ss * (1.0f / 64.0f) + 1.1920929e-07f);
        v0 *= sc; v1 *= sc; v2 *= sc; v3 *= sc;

        float p0 = __shfl_xor_sync(~0u, v0, 8);
        float p1 = __shfl_xor_sync(~0u, v1, 8);
        float p2 = __shfl_xor_sync(~0u, v2, 8);
        float p3 = __shfl_xor_sync(~0u, v3, 8);

        float o0, o1, o2, o3;
        if (lo_half) {
            o0 = v0 * csv[0] + p0 * snv[0];
            o1 = v1 * csv[1] + p1 * snv[1];
            o2 = v2 * csv[2] + p2 * snv[2];
            o3 = v3 * csv[3] + p3 * snv[3];
        } else {
            o0 = v0 * csv[0] - p0 * snv[0];
            o1 = v1 * csv[1] - p1 * snv[1];
            o2 = v2 * csv[2] - p2 * snv[2];
            o3 = v3 * csv[3] - p3 * snv[3];
        }

        const size_t idx = (size_t)(m0 + ty * 8 + r) * 2048 + s * 128 + off + tx * 4;
        *(half2*)&Hbuf[idx]     = __floats2half2_rn(o0 * scale, o1 * scale);
        *(half2*)&Hbuf[idx + 2] = __floats2half2_rn(o2 * scale, o3 * scale);
    }
}

// ---------------------------------------------------------------------------
// Tensor-core causal flash, one wave of 8 heads. Internals as R12/R13 except:
//  - q-tile REVERSED (longest blocks scheduled first: q0 = (31-bx)*64)
//  - y overwrites the Q half-strip in place (read-before-write within block)
// ---------------------------------------------------------------------------
__global__ __launch_bounds__(256) void flash_mma(half* __restrict__ Hbuf, int hbase)
{
    __shared__ half Qh[64 * 72];
    __shared__ half Kh[64 * 72];
    __shared__ half Vt[64 * 72];
    __shared__ half Ph[64 * 72];
    __shared__ float redm[2][64];
    __shared__ float reds[2][64];

    const int tid  = threadIdx.x;
    const int lane = tid & 31;
    const int w    = tid >> 5;
    const int gid  = lane >> 2;
    const int tq   = lane & 3;
    const int wq   = (w >> 1) * 16;
    const int wk   = (w & 1) * 32;
    const int wc   = w & 1;

    const int hl = blockIdx.z;
    const int h  = hbase + hl;
    const int b  = blockIdx.y;
    const int qx = 31 - blockIdx.x;      // reversed: longest first
    const int q0 = qx * 64;
    const int kvs = hl;
    const int qs  = 8 + (h >> 1);
    const int qoff = (h & 1) * 64;
    // y overwrites Q in place:
    const int ys  = qs;
    const int yoff = qoff;

    #pragma unroll
    for (int i = 0; i < 2; i++) {
        int f = tid + i * 256;
        int r = f >> 3;
        int c = (f & 7) * 8;
        *(int4*)&Qh[r * 72 + c] =
            *(const int4*)&Hbuf[(size_t)(b * 2048 + q0 + r) * 2048 + qs * 128 + qoff + c];
    }
    __syncthreads();

    unsigned aq[4][4];
    #pragma unroll
    for (int kt = 0; kt < 4; kt++) {
        int col = kt * 16 + 2 * tq;
        aq[kt][0] = *(const unsigned*)&Qh[(wq + gid) * 72 + col];
        aq[kt][1] = *(const unsigned*)&Qh[(wq + gid + 8) * 72 + col];
        aq[kt][2] = *(const unsigned*)&Qh[(wq + gid) * 72 + col + 8];
        aq[kt][3] = *(const unsigned*)&Qh[(wq + gid + 8) * 72 + col + 8];
    }

    float m0v = -1e30f, m1v = -1e30f, l0v = 0.f, l1v = 0.f;
    float oa[4][4];
    #pragma unroll
    for (int nt = 0; nt < 4; nt++)
        #pragma unroll
        for (int c = 0; c < 4; c++) oa[nt][c] = 0.f;

    const int ntiles = qx + 1;
    for (int it = 0; it < ntiles; it++) {
        const int k0 = it * 64;
        __syncthreads();

        #pragma unroll
        for (int i = 0; i < 2; i++) {
            int f = tid + i * 256;
            int r = f >> 3;
            int c = (f & 7) * 8;
            *(int4*)&Kh[r * 72 + c] =
                *(const int4*)&Hbuf[(size_t)(b * 2048 + k0 + r) * 2048 + kvs * 128 + c];
        }
        #pragma unroll
        for (int i = 0; i < 8; i++) {
            int f  = tid + i * 256;
            int r  = f >> 5;
            int c2 = f & 31;
            half2 v = *(const half2*)&Hbuf[(size_t)(b * 2048 + k0 + r) * 2048 + kvs * 128 + 64 + c2 * 2];
            Vt[(2 * c2 + 0) * 72 + r] = __low2half(v);
            Vt[(2 * c2 + 1) * 72 + r] = __high2half(v);
        }
        __syncthreads();

        float sacc[4][4];
        #pragma unroll
        for (int nt = 0; nt < 4; nt++)
            #pragma unroll
            for (int c = 0; c < 4; c++) sacc[nt][c] = 0.f;

        #pragma unroll
        for (int kt = 0; kt < 4; kt++) {
            #pragma unroll
            for (int nt = 0; nt < 4; nt++) {
                int krow = (wk + nt * 8 + gid) * 72 + kt * 16 + 2 * tq;
                unsigned bk0 = *(const unsigned*)&Kh[krow];
                unsigned bk1 = *(const unsigned*)&Kh[krow + 8];
                mma16816(sacc[nt], aq[kt], bk0, bk1);
            }
        }

        if (k0 == q0) {
            #pragma unroll
            for (int nt = 0; nt < 4; nt++)
                #pragma unroll
                for (int c = 0; c < 4; c++) {
                    int col = wk + nt * 8 + 2 * tq + (c & 1);
                    int row = wq + gid + ((c >> 1) * 8);
                    if (col > row) sacc[nt][c] = -1e30f;
                }
        }

        float tm0 = -1e30f, tm1 = -1e30f;
        #pragma unroll
        for (int nt = 0; nt < 4; nt++) {
            tm0 = fmaxf(tm0, fmaxf(sacc[nt][0], sacc[nt][1]));
            tm1 = fmaxf(tm1, fmaxf(sacc[nt][2], sacc[nt][3]));
        }
        tm0 = fmaxf(tm0, __shfl_xor_sync(~0u, tm0, 1));
        tm0 = fmaxf(tm0, __shfl_xor_sync(~0u, tm0, 2));
        tm1 = fmaxf(tm1, __shfl_xor_sync(~0u, tm1, 1));
        tm1 = fmaxf(tm1, __shfl_xor_sync(~0u, tm1, 2));
        if (tq == 0) {
            redm[wc][wq + gid]     = tm0;
            redm[wc][wq + gid + 8] = tm1;
        }
        __syncthreads();
        float mn0 = fmaxf(m0v, fmaxf(redm[0][wq + gid],     redm[1][wq + gid]));
        float mn1 = fmaxf(m1v, fmaxf(redm[0][wq + gid + 8], redm[1][wq + gid + 8]));
        float alpha0 = __expf(m0v - mn0);
        float alpha1 = __expf(m1v - mn1);
        m0v = mn0; m1v = mn1;

        float ts0 = 0.f, ts1 = 0.f;
        #pragma unroll
        for (int nt = 0; nt < 4; nt++) {
            sacc[nt][0] = __expf(sacc[nt][0] - mn0);
            sacc[nt][1] = __expf(sacc[nt][1] - mn0);
            sacc[nt][2] = __expf(sacc[nt][2] - mn1);
            sacc[nt][3] = __expf(sacc[nt][3] - mn1);
            ts0 += sacc[nt][0] + sacc[nt][1];
            ts1 += sacc[nt][2] + sacc[nt][3];
            int col = wk + nt * 8 + 2 * tq;
            *(half2*)&Ph[(wq + gid) * 72 + col]     = __floats2half2_rn(sacc[nt][0], sacc[nt][1]);
            *(half2*)&Ph[(wq + gid + 8) * 72 + col] = __floats2half2_rn(sacc[nt][2], sacc[nt][3]);
        }
        ts0 += __shfl_xor_sync(~0u, ts0, 1);
        ts0 += __shfl_xor_sync(~0u, ts0, 2);
        ts1 += __shfl_xor_sync(~0u, ts1, 1);
        ts1 += __shfl_xor_sync(~0u, ts1, 2);
        if (tq == 0) {
            reds[wc][wq + gid]     = ts0;
            reds[wc][wq + gid + 8] = ts1;
        }

        #pragma unroll
        for (int nt = 0; nt < 4; nt++) {
            oa[nt][0] *= alpha0;
            oa[nt][1] *= alpha0;
            oa[nt][2] *= alpha1;
            oa[nt][3] *= alpha1;
        }
        __syncthreads();
        l0v = l0v * alpha0 + reds[0][wq + gid]     + reds[1][wq + gid];
        l1v = l1v * alpha1 + reds[0][wq + gid + 8] + reds[1][wq + gid + 8];

        #pragma unroll
        for (int jt = 0; jt < 4; jt++) {
            int col = jt * 16 + 2 * tq;
            unsigned ap[4];
            ap[0] = *(const unsigned*)&Ph[(wq + gid) * 72 + col];
            ap[1] = *(const unsigned*)&Ph[(wq + gid + 8) * 72 + col];
            ap[2] = *(const unsigned*)&Ph[(wq + gid) * 72 + col + 8];
            ap[3] = *(const unsigned*)&Ph[(wq + gid + 8) * 72 + col + 8];
            #pragma unroll
            for (int nt = 0; nt < 4; nt++) {
                int vrow = (wk + nt * 8 + gid) * 72 + col;
                unsigned bv0 = *(const unsigned*)&Vt[vrow];
                unsigned bv1 = *(const unsigned*)&Vt[vrow + 8];
                mma16816(oa[nt], ap, bv0, bv1);
            }
        }
    }

    float inv0 = 1.0f / l0v;
    float inv1 = 1.0f / l1v;
    const size_t row0 = (size_t)(b * 2048 + q0 + wq + gid);
    const size_t row1 = row0 + 8;
    #pragma unroll
    for (int nt = 0; nt < 4; nt++) {
        int col = wk + nt * 8 + 2 * tq;
        *(half2*)&Hbuf[row0 * 2048 + ys * 128 + yoff + col] =
            __floats2half2_rn(oa[nt][0] * inv0, oa[nt][1] * inv0);
        *(half2*)&Hbuf[row1 * 2048 + ys * 128 + yoff + col] =
            __floats2half2_rn(oa[nt][2] * inv1, oa[nt][3] * inv1);
    }
}

// ---------------------------------------------------------------------------
// proj (tensor-core, in-place): unchanged from R13 except y strip map
// (strip 8+(h>>1), half h&1).
// ---------------------------------------------------------------------------
__global__ __launch_bounds__(256) void proj_kernel(
    const float* __restrict__ Wp, const float* __restrict__ bp,
    float* __restrict__ out)
{
    extern __shared__ char dsm[];
    half* ysm = (half*)dsm;             // [32][1032]
    half* Ws  = ysm + 32 * 1032;        // [128][66]

    const half* Hbuf = (const half*)out;
    const int tid  = threadIdx.x;
    const int lane = tid & 31;
    const int w    = tid >> 5;
    const int gid  = lane >> 2;
    const int tq   = lane & 3;
    const int wm   = (w >> 2) * 16;
    const int wn   = (w & 3) * 32;
    const int m0   = blockIdx.x * 32;

    #pragma unroll
    for (int i = 0; i < 64; i++) {
        int f  = tid + i * 256;
        int r  = f >> 9;
        int c2 = f & 511;
        int hh = c2 >> 5;
        int d2 = c2 & 31;
        int ys = 8 + (hh >> 1);
        int yh = hh & 1;
        half2 v = *(const half2*)&Hbuf[(size_t)(m0 + r) * 2048 + ys * 128 + yh * 64 + d2 * 2];
        *(half2*)&ysm[r * 1032 + c2 * 2] = v;
    }
    __syncthreads();

    for (int ntile = 0; ntile < 8; ntile++) {
        float acc[4][4];
        #pragma unroll
        for (int nt = 0; nt < 4; nt++)
            #pragma unroll
            for (int c = 0; c < 4; c++) acc[nt][c] = 0.f;

        for (int k0 = 0; k0 < C_; k0 += 64) {
            __syncthreads();
            #pragma unroll
            for (int i = 0; i < 16; i++) {
                int f  = tid + i * 256;
                int n2 = f & 63;
                int k  = f >> 6;
                float2 wv = *(const float2*)&Wp[(size_t)(k0 + k) * C_ + ntile * 128 + 2 * n2];
                Ws[(2 * n2 + 0) * 66 + k] = __float2half_rn(wv.x);
                Ws[(2 * n2 + 1) * 66 + k] = __float2half_rn(wv.y);
            }
            __syncthreads();

            #pragma unroll
            for (int kt = 0; kt < 4; kt++) {
                int col = k0 + kt * 16 + 2 * tq;
                unsigned af[4];
                af[0] = *(const unsigned*)&ysm[(wm + gid) * 1032 + col];
                af[1] = *(const unsigned*)&ysm[(wm + gid + 8) * 1032 + col];
                af[2] = *(const unsigned*)&ysm[(wm + gid) * 1032 + col + 8];
                af[3] = *(const unsigned*)&ysm[(wm + gid + 8) * 1032 + col + 8];
                #pragma unroll
                for (int nt = 0; nt < 4; nt++) {
                    int nrow = (wn + nt * 8 + gid) * 66 + kt * 16 + 2 * tq;
                    unsigned b0 = *(const unsigned*)&Ws[nrow];
                    unsigned b1 = *(const unsigned*)&Ws[nrow + 8];
                    mma16816(acc[nt], af, b0, b1);
                }
            }
        }

        #pragma unroll
        for (int nt = 0; nt < 4; nt++) {
            int col = ntile * 128 + wn + nt * 8 + 2 * tq;
            float2 bb = *(const float2*)&bp[col];
            size_t r0 = (size_t)(m0 + wm + gid);
            *(float2*)&out[r0 * C_ + col] =
                make_float2(acc[nt][0] + bb.x, acc[nt][1] + bb.y);
            *(float2*)&out[(r0 + 8) * C_ + col] =
                make_float2(acc[nt][2] + bb.x, acc[nt][3] + bb.y);
        }
    }
}

// ---------------------------------------------------------------------------
extern "C" void kernel_launch(void* const* d_in, const int* in_sizes, int n_in,
                              void* d_out, int out_size)
{
    const float* x      = (const float*)d_in[0];
    const float* W_attn = (const float*)d_in[1];
    const float* b_attn = (const float*)d_in[2];
    const float* W_proj = (const float*)d_in[3];
    const float* b_proj = (const float*)d_in[4];
    float* out  = (float*)d_out;
    half*  Hbuf = (half*)d_out;

    const int kvq_smem  = 128 * 68 * 4;                    // 34816
    const int proj_smem = 32 * 1032 * 2 + 128 * 66 * 2;    // 82944

    cudaFuncSetAttribute(proj_kernel, cudaFuncAttributeMaxDynamicSharedMemorySize, proj_smem);

    // 2 waves of 8 heads; y overwrites Q strips in place.
    for (int wv = 0; wv < 2; wv++) {
        const int hbase = wv * 8;
        kvq_kernel<<<dim3(24, M_ / 128), 256, kvq_smem>>>(x, W_attn, b_attn, Hbuf, hbase);
        flash_mma<<<dim3(T_ / 64, B_, 8), 256>>>(Hbuf, hbase);
    }

    proj_kernel<<<128, 256, proj_smem>>>(W_proj, b_proj, out);
}

// round 16
// speedup vs baseline: 3.2580x; 1.0475x over previous
#include <cuda_runtime.h>
#include <cuda_fp16.h>
#include <math.h>
#include <string.h>

// Problem constants
#define B_  2
#define T_  2048
#define C_  1024
#define H_  16
#define D_  64
#define M_  (B_*T_)          // 4096
#define N3_ (3*C_)           // 3072

// NO __device__ globals, NO static initializers (R2-R10: any module data
// segment triggers a 128 MiB driver slab inside the checkpointed run).
// All scratch lives in d_out (16 MiB = 4096 rows x 2048 halfs), in "strips":
// strip s of row m = halfs [m*2048 + s*128, +128).
//
// 2 head-waves of 8. Per wave (local head hl = h - hbase):
//   K fp16 -> strip hl, off 0;  V fp16 -> strip hl, off 64
//   Q fp16 -> strip 8+(h>>1), off (h&1)*64   (wave0: s8-11, wave1: s12-15)
//   y fp16 OVERWRITES Q in place (block reads its Q rows into registers
//   before writing y to the same location; other blocks touch disjoint rows).
// proj reads y at strip 8+(h>>1), half h&1, for all 16 heads.

// ---------------------------------------------------------------------------
// bit-cast helper (the __half2_as_uint intrinsic doesn't exist here)
// ---------------------------------------------------------------------------
__device__ __forceinline__ unsigned h2_as_u32(half2 v)
{
    unsigned u;
    memcpy(&u, &v, 4);
    return u;
}

// ---------------------------------------------------------------------------
// mma helper: m16n8k16 row.col f32 = f16 x f16 + f32
// ---------------------------------------------------------------------------
__device__ __forceinline__ void mma16816(
    float c[4], const unsigned a[4], unsigned b0, unsigned b1)
{
    asm volatile(
        "mma.sync.aligned.m16n8k16.row.col.f32.f16.f16.f32 "
        "{%0,%1,%2,%3}, {%4,%5,%6,%7}, {%8,%9}, {%0,%1,%2,%3};"
        : "+f"(c[0]), "+f"(c[1]), "+f"(c[2]), "+f"(c[3])
        : "r"(a[0]), "r"(a[1]), "r"(a[2]), "r"(a[3]), "r"(b0), "r"(b1));
}

// ---------------------------------------------------------------------------
// kvq (tensor-core): fused QKV GEMM + bias (+ RMS-norm + rotary for K/Q) for
// one wave of 8 heads. Unchanged from R13/R14 (verified).
// ---------------------------------------------------------------------------
__global__ __launch_bounds__(256) void kvq_kernel(
    const float* __restrict__ x, const float* __restrict__ Wa,
    const float* __restrict__ ba, half* __restrict__ Hbuf, int hbase)
{
    extern __shared__ char dsm[];
    half*  Xs = (half*)dsm;             // [128][66]
    half*  Ws = Xs + 128 * 66;          // [64][66]
    float* Es = (float*)dsm;            // [128][68] overlay

    const int tid  = threadIdx.x;
    const int lane = tid & 31;
    const int w    = tid >> 5;
    const int gid  = lane >> 2;
    const int tq   = lane & 3;
    const int wm   = (w >> 1) * 32;
    const int wn   = (w & 1) * 32;

    const int m0   = blockIdx.y * 128;
    const int hl   = blockIdx.x / 3;
    const int kind = blockIdx.x % 3;              // 0=K, 1=V, 2=Q
    const int h    = hbase + hl;
    const int n0   = (kind == 0 ? C_ : (kind == 1 ? 2 * C_ : 0)) + h * 64;
    const int s    = (kind == 2) ? (8 + (h >> 1)) : hl;
    const int off  = (kind == 2) ? ((h & 1) * 64) : (kind == 1 ? 64 : 0);

    float acc[2][4][4];
    #pragma unroll
    for (int mt = 0; mt < 2; mt++)
        #pragma unroll
        for (int nt = 0; nt < 4; nt++)
            #pragma unroll
            for (int c = 0; c < 4; c++) acc[mt][nt][c] = 0.f;

    for (int k0 = 0; k0 < C_; k0 += 64) {
        __syncthreads();
        #pragma unroll
        for (int i = 0; i < 8; i++) {
            int f  = tid + i * 256;
            int m  = f >> 4;
            int kc = (f & 15) * 4;
            float4 a4 = *(const float4*)&x[(size_t)(m0 + m) * C_ + k0 + kc];
            *(half2*)&Xs[m * 66 + kc]     = __floats2half2_rn(a4.x, a4.y);
            *(half2*)&Xs[m * 66 + kc + 2] = __floats2half2_rn(a4.z, a4.w);
        }
        #pragma unroll
        for (int i = 0; i < 8; i++) {
            int f  = tid + i * 256;
            int n2 = f & 31;
            int k  = f >> 5;
            float2 wv = *(const float2*)&Wa[(size_t)(k0 + k) * N3_ + n0 + 2 * n2];
            Ws[(2 * n2 + 0) * 66 + k] = __float2half_rn(wv.x);
            Ws[(2 * n2 + 1) * 66 + k] = __float2half_rn(wv.y);
        }
        __syncthreads();

        #pragma unroll
        for (int kt = 0; kt < 4; kt++) {
            unsigned af[2][4];
            #pragma unroll
            for (int mt = 0; mt < 2; mt++) {
                int row = wm + mt * 16 + gid;
                int col = kt * 16 + 2 * tq;
                af[mt][0] = *(const unsigned*)&Xs[row * 66 + col];
                af[mt][1] = *(const unsigned*)&Xs[(row + 8) * 66 + col];
                af[mt][2] = *(const unsigned*)&Xs[row * 66 + col + 8];
                af[mt][3] = *(const unsigned*)&Xs[(row + 8) * 66 + col + 8];
            }
            #pragma unroll
            for (int nt = 0; nt < 4; nt++) {
                int nrow = (wn + nt * 8 + gid) * 66 + kt * 16 + 2 * tq;
                unsigned b0 = *(const unsigned*)&Ws[nrow];
                unsigned b1 = *(const unsigned*)&Ws[nrow + 8];
                mma16816(acc[0][nt], af[0], b0, b1);
                mma16816(acc[1][nt], af[1], b0, b1);
            }
        }
    }

    __syncthreads();
    #pragma unroll
    for (int mt = 0; mt < 2; mt++)
        #pragma unroll
        for (int nt = 0; nt < 4; nt++) {
            int r0 = wm + mt * 16 + gid;
            int c  = wn + nt * 8 + 2 * tq;
            *(float2*)&Es[r0 * 68 + c]       = make_float2(acc[mt][nt][0], acc[mt][nt][1]);
            *(float2*)&Es[(r0 + 8) * 68 + c] = make_float2(acc[mt][nt][2], acc[mt][nt][3]);
        }
    __syncthreads();

    const int tx = tid & 15;
    const int ty = tid >> 4;

    float4 bv = *(const float4*)&ba[n0 + tx * 4];
    const float bias_c[4] = {bv.x, bv.y, bv.z, bv.w};

    if (kind == 1) {
        #pragma unroll
        for (int r = 0; r < 8; r++) {
            float4 v4 = *(float4*)&Es[(ty * 8 + r) * 68 + tx * 4];
            const size_t idx = (size_t)(m0 + ty * 8 + r) * 2048 + s * 128 + off + tx * 4;
            *(half2*)&Hbuf[idx]     = __floats2half2_rn(v4.x + bias_c[0], v4.y + bias_c[1]);
            *(half2*)&Hbuf[idx + 2] = __floats2half2_rn(v4.z + bias_c[2], v4.w + bias_c[3]);
        }
        return;
    }

    float csv[4], snv[4];
    #pragma unroll
    for (int c = 0; c < 4; c++) {
        int j = ((tx & 7) * 4) + c;
        float ang = (float)h * __expf(-(float)j * 0.28782313662425572f);
        __sincosf(ang, &snv[c], &csv[c]);
    }
    const float scale = (kind == 2) ? 0.125f : 1.0f;
    const bool lo_half = (tx < 8);

    #pragma unroll
    for (int r = 0; r < 8; r++) {
        float4 v4 = *(float4*)&Es[(ty * 8 + r) * 68 + tx * 4];
        float v0 = v4.x + bias_c[0];
        float v1 = v4.y + bias_c[1];
        float v2 = v4.z + bias_c[2];
        float v3 = v4.w + bias_c[3];

        float ss = v0 * v0 + v1 * v1 + v2 * v2 + v3 * v3;
        ss += __shfl_xor_sync(~0u, ss, 1);
        ss += __shfl_xor_sync(~0u, ss, 2);
        ss += __shfl_xor_sync(~0u, ss, 4);
        ss += __shfl_xor_sync(~0u, ss, 8);
        float sc = rsqrtf(ss * (1.0f / 64.0f) + 1.1920929e-07f);
        v0 *= sc; v1 *= sc; v2 *= sc; v3 *= sc;

        float p0 = __shfl_xor_sync(~0u, v0, 8);
        float p1 = __shfl_xor_sync(~0u, v1, 8);
        float p2 = __shfl_xor_sync(~0u, v2, 8);
        float p3 = __shfl_xor_sync(~0u, v3, 8);

        float o0, o1, o2, o3;
        if (lo_half) {
            o0 = v0 * csv[0] + p0 * snv[0];
            o1 = v1 * csv[1] + p1 * snv[1];
            o2 = v2 * csv[2] + p2 * snv[2];
            o3 = v3 * csv[3] + p3 * snv[3];
        } else {
            o0 = v0 * csv[0] - p0 * snv[0];
            o1 = v1 * csv[1] - p1 * snv[1];
            o2 = v2 * csv[2] - p2 * snv[2];
            o3 = v3 * csv[3] - p3 * snv[3];
        }

        const size_t idx = (size_t)(m0 + ty * 8 + r) * 2048 + s * 128 + off + tx * 4;
        *(half2*)&Hbuf[idx]     = __floats2half2_rn(o0 * scale, o1 * scale);
        *(half2*)&Hbuf[idx + 2] = __floats2half2_rn(o2 * scale, o3 * scale);
    }
}

// ---------------------------------------------------------------------------
// FA2-style tensor-core causal flash, one wave of 8 heads.
// 8 warps = 4(q) x 2(j). Each warp keeps PRIVATE (m, l, O) for its 32-col
// j-slice; P stays in registers (mma accumulator fragments repack directly
// into A fragments); O covers the full d=64 per warp. One cross-warp merge
// at the epilogue (m/l exchange + O add via smem overlay on Kh/Vt).
// 2 __syncthreads per KV tile. q-tiles reversed (longest first); y
// overwrites the Q half-strip in place.
// ---------------------------------------------------------------------------
__global__ __launch_bounds__(256) void flash_mma(half* __restrict__ Hbuf, int hbase)
{
    __shared__ __align__(16) char smraw[28672];
    half*  Qh  = (half*)smraw;                    // [64][72]
    half*  Kh  = (half*)(smraw + 9216);           // [64][72]
    half*  Vt  = (half*)(smraw + 18432);          // [64][72] (Vt[d][j])
    float* Msm = (float*)(smraw + 27648);         // [2][64]
    float* Lsm = (float*)(smraw + 28160);         // [2][64]
    float* Osm = (float*)(smraw + 9216);          // overlay Kh+Vt, [64][68]

    const int tid  = threadIdx.x;
    const int lane = tid & 31;
    const int w    = tid >> 5;
    const int gid  = lane >> 2;
    const int tq   = lane & 3;
    const int wq   = (w >> 1) * 16;      // warp q offset
    const int wc   = w & 1;              // warp column (j-slice id)
    const int wk   = wc * 32;            // warp j offset

    const int hl = blockIdx.z;
    const int h  = hbase + hl;
    const int b  = blockIdx.y;
    const int qx = 31 - blockIdx.x;      // reversed: longest first
    const int q0 = qx * 64;
    const int kvs = hl;
    const int qs  = 8 + (h >> 1);
    const int qoff = (h & 1) * 64;

    // ---- load Q tile ----
    #pragma unroll
    for (int i = 0; i < 2; i++) {
        int f = tid + i * 256;
        int r = f >> 3;
        int c = (f & 7) * 8;
        *(int4*)&Qh[r * 72 + c] =
            *(const int4*)&Hbuf[(size_t)(b * 2048 + q0 + r) * 2048 + qs * 128 + qoff + c];
    }
    __syncthreads();

    unsigned aq[4][4];
    #pragma unroll
    for (int kt = 0; kt < 4; kt++) {
        int col = kt * 16 + 2 * tq;
        aq[kt][0] = *(const unsigned*)&Qh[(wq + gid) * 72 + col];
        aq[kt][1] = *(const unsigned*)&Qh[(wq + gid + 8) * 72 + col];
        aq[kt][2] = *(const unsigned*)&Qh[(wq + gid) * 72 + col + 8];
        aq[kt][3] = *(const unsigned*)&Qh[(wq + gid + 8) * 72 + col + 8];
    }

    float m0v = -1e30f, m1v = -1e30f, l0v = 0.f, l1v = 0.f;
    float oa[8][4];
    #pragma unroll
    for (int dt = 0; dt < 8; dt++)
        #pragma unroll
        for (int c = 0; c < 4; c++) oa[dt][c] = 0.f;

    const int ntiles = qx + 1;
    for (int it = 0; it < ntiles; it++) {
        const int k0 = it * 64;
        __syncthreads();   // prior tile's Kh/Vt reads done

        #pragma unroll
        for (int i = 0; i < 2; i++) {
            int f = tid + i * 256;
            int r = f >> 3;
            int c = (f & 7) * 8;
            *(int4*)&Kh[r * 72 + c] =
                *(const int4*)&Hbuf[(size_t)(b * 2048 + k0 + r) * 2048 + kvs * 128 + c];
        }
        #pragma unroll
        for (int i = 0; i < 8; i++) {
            int f  = tid + i * 256;
            int r  = f >> 5;
            int c2 = f & 31;
            half2 v = *(const half2*)&Hbuf[(size_t)(b * 2048 + k0 + r) * 2048 + kvs * 128 + 64 + c2 * 2];
            Vt[(2 * c2 + 0) * 72 + r] = __low2half(v);
            Vt[(2 * c2 + 1) * 72 + r] = __high2half(v);
        }
        __syncthreads();

        // ---- score S = Q K^T (warp: 16q x 32j at wk) ----
        float sacc[4][4];
        #pragma unroll
        for (int nt = 0; nt < 4; nt++)
            #pragma unroll
            for (int c = 0; c < 4; c++) sacc[nt][c] = 0.f;

        #pragma unroll
        for (int kt = 0; kt < 4; kt++) {
            #pragma unroll
            for (int nt = 0; nt < 4; nt++) {
                int krow = (wk + nt * 8 + gid) * 72 + kt * 16 + 2 * tq;
                unsigned bk0 = *(const unsigned*)&Kh[krow];
                unsigned bk1 = *(const unsigned*)&Kh[krow + 8];
                mma16816(sacc[nt], aq[kt], bk0, bk1);
            }
        }

        if (k0 == q0) {
            #pragma unroll
            for (int nt = 0; nt < 4; nt++)
                #pragma unroll
                for (int c = 0; c < 4; c++) {
                    int col = wk + nt * 8 + 2 * tq + (c & 1);
                    int row = wq + gid + ((c >> 1) * 8);
                    if (col > row) sacc[nt][c] = -1e30f;
                }
        }

        // ---- warp-private online softmax (quad shuffles only) ----
        float tm0 = -1e30f, tm1 = -1e30f;
        #pragma unroll
        for (int nt = 0; nt < 4; nt++) {
            tm0 = fmaxf(tm0, fmaxf(sacc[nt][0], sacc[nt][1]));
            tm1 = fmaxf(tm1, fmaxf(sacc[nt][2], sacc[nt][3]));
        }
        tm0 = fmaxf(tm0, __shfl_xor_sync(~0u, tm0, 1));
        tm0 = fmaxf(tm0, __shfl_xor_sync(~0u, tm0, 2));
        tm1 = fmaxf(tm1, __shfl_xor_sync(~0u, tm1, 1));
        tm1 = fmaxf(tm1, __shfl_xor_sync(~0u, tm1, 2));
        float mn0 = fmaxf(m0v, tm0);
        float mn1 = fmaxf(m1v, tm1);
        float alpha0 = __expf(m0v - mn0);
        float alpha1 = __expf(m1v - mn1);
        m0v = mn0; m1v = mn1;

        float ts0 = 0.f, ts1 = 0.f;
        unsigned plo[4], phi[4];
        #pragma unroll
        for (int nt = 0; nt < 4; nt++) {
            float e0 = __expf(sacc[nt][0] - mn0);
            float e1 = __expf(sacc[nt][1] - mn0);
            float e2 = __expf(sacc[nt][2] - mn1);
            float e3 = __expf(sacc[nt][3] - mn1);
            ts0 += e0 + e1;
            ts1 += e2 + e3;
            plo[nt] = h2_as_u32(__floats2half2_rn(e0, e1));
            phi[nt] = h2_as_u32(__floats2half2_rn(e2, e3));
        }
        ts0 += __shfl_xor_sync(~0u, ts0, 1);
        ts0 += __shfl_xor_sync(~0u, ts0, 2);
        ts1 += __shfl_xor_sync(~0u, ts1, 1);
        ts1 += __shfl_xor_sync(~0u, ts1, 2);
        l0v = l0v * alpha0 + ts0;
        l1v = l1v * alpha1 + ts1;

        #pragma unroll
        for (int dt = 0; dt < 8; dt++) {
            oa[dt][0] *= alpha0;
            oa[dt][1] *= alpha0;
            oa[dt][2] *= alpha1;
            oa[dt][3] *= alpha1;
        }

        // ---- O += P V (P in registers; warp: 16q x 64d, its 32 j) ----
        #pragma unroll
        for (int jt = 0; jt < 2; jt++) {
            unsigned ap[4];
            ap[0] = plo[jt * 2 + 0];
            ap[1] = phi[jt * 2 + 0];
            ap[2] = plo[jt * 2 + 1];
            ap[3] = phi[jt * 2 + 1];
            #pragma unroll
            for (int dt = 0; dt < 8; dt++) {
                int vrow = (dt * 8 + gid) * 72 + wk + jt * 16 + 2 * tq;
                unsigned bv0 = *(const unsigned*)&Vt[vrow];
                unsigned bv1 = *(const unsigned*)&Vt[vrow + 8];
                mma16816(oa[dt], ap, bv0, bv1);
            }
        }
    }

    // ---- epilogue: merge the 2 warp columns, normalize, write y ----
    const int row0 = wq + gid;
    const int row1 = row0 + 8;
    __syncthreads();
    if (tq == 0) {
        Msm[wc * 64 + row0] = m0v;
        Msm[wc * 64 + row1] = m1v;
    }
    __syncthreads();
    float mf0 = fmaxf(Msm[row0], Msm[64 + row0]);
    float mf1 = fmaxf(Msm[row1], Msm[64 + row1]);
    float fac0 = __expf(m0v - mf0);
    float fac1 = __expf(m1v - mf1);
    if (tq == 0) {
        Lsm[wc * 64 + row0] = l0v * fac0;
        Lsm[wc * 64 + row1] = l1v * fac1;
    }
    #pragma unroll
    for (int dt = 0; dt < 8; dt++) {
        oa[dt][0] *= fac0;
        oa[dt][1] *= fac0;
        oa[dt][2] *= fac1;
        oa[dt][3] *= fac1;
    }
    __syncthreads();
    float lt0 = Lsm[row0] + Lsm[64 + row0];
    float lt1 = Lsm[row1] + Lsm[64 + row1];
    if (wc == 1) {
        #pragma unroll
        for (int dt = 0; dt < 8; dt++) {
            int col = dt * 8 + 2 * tq;
            *(float2*)&Osm[row0 * 68 + col] = make_float2(oa[dt][0], oa[dt][1]);
            *(float2*)&Osm[row1 * 68 + col] = make_float2(oa[dt][2], oa[dt][3]);
        }
    }
    __syncthreads();
    if (wc == 0) {
        float inv0 = 1.0f / lt0;
        float inv1 = 1.0f / lt1;
        const size_t r0g = (size_t)(b * 2048 + q0 + row0);
        const size_t r1g = r0g + 8;
        #pragma unroll
        for (int dt = 0; dt < 8; dt++) {
            int col = dt * 8 + 2 * tq;
            float2 p0 = *(float2*)&Osm[row0 * 68 + col];
            float2 p1 = *(float2*)&Osm[row1 * 68 + col];
            *(half2*)&Hbuf[r0g * 2048 + qs * 128 + qoff + col] =
                __floats2half2_rn((oa[dt][0] + p0.x) * inv0, (oa[dt][1] + p0.y) * inv0);
            *(half2*)&Hbuf[r1g * 2048 + qs * 128 + qoff + col] =
                __floats2half2_rn((oa[dt][2] + p1.x) * inv1, (oa[dt][3] + p1.y) * inv1);
        }
    }
}

// ---------------------------------------------------------------------------
// proj (tensor-core, in-place): unchanged from R14 (verified).
// ---------------------------------------------------------------------------
__global__ __launch_bounds__(256) void proj_kernel(
    const float* __restrict__ Wp, const float* __restrict__ bp,
    float* __restrict__ out)
{
    extern __shared__ char dsm[];
    half* ysm = (half*)dsm;             // [32][1032]
    half* Ws  = ysm + 32 * 1032;        // [128][66]

    const half* Hbuf = (const half*)out;
    const int tid  = threadIdx.x;
    const int lane = tid & 31;
    const int w    = tid >> 5;
    const int gid  = lane >> 2;
    const int tq   = lane & 3;
    const int wm   = (w >> 2) * 16;
    const int wn   = (w & 3) * 32;
    const int m0   = blockIdx.x * 32;

    #pragma unroll
    for (int i = 0; i < 64; i++) {
        int f  = tid + i * 256;
        int r  = f >> 9;
        int c2 = f & 511;
        int hh = c2 >> 5;
        int d2 = c2 & 31;
        int ys = 8 + (hh >> 1);
        int yh = hh & 1;
        half2 v = *(const half2*)&Hbuf[(size_t)(m0 + r) * 2048 + ys * 128 + yh * 64 + d2 * 2];
        *(half2*)&ysm[r * 1032 + c2 * 2] = v;
    }
    __syncthreads();

    for (int ntile = 0; ntile < 8; ntile++) {
        float acc[4][4];
        #pragma unroll
        for (int nt = 0; nt < 4; nt++)
            #pragma unroll
            for (int c = 0; c < 4; c++) acc[nt][c] = 0.f;

        for (int k0 = 0; k0 < C_; k0 += 64) {
            __syncthreads();
            #pragma unroll
            for (int i = 0; i < 16; i++) {
                int f  = tid + i * 256;
                int n2 = f & 63;
                int k  = f >> 6;
                float2 wv = *(const float2*)&Wp[(size_t)(k0 + k) * C_ + ntile * 128 + 2 * n2];
                Ws[(2 * n2 + 0) * 66 + k] = __float2half_rn(wv.x);
                Ws[(2 * n2 + 1) * 66 + k] = __float2half_rn(wv.y);
            }
            __syncthreads();

            #pragma unroll
            for (int kt = 0; kt < 4; kt++) {
                int col = k0 + kt * 16 + 2 * tq;
                unsigned af[4];
                af[0] = *(const unsigned*)&ysm[(wm + gid) * 1032 + col];
                af[1] = *(const unsigned*)&ysm[(wm + gid + 8) * 1032 + col];
                af[2] = *(const unsigned*)&ysm[(wm + gid) * 1032 + col + 8];
                af[3] = *(const unsigned*)&ysm[(wm + gid + 8) * 1032 + col + 8];
                #pragma unroll
                for (int nt = 0; nt < 4; nt++) {
                    int nrow = (wn + nt * 8 + gid) * 66 + kt * 16 + 2 * tq;
                    unsigned b0 = *(const unsigned*)&Ws[nrow];
                    unsigned b1 = *(const unsigned*)&Ws[nrow + 8];
                    mma16816(acc[nt], af, b0, b1);
                }
            }
        }

        #pragma unroll
        for (int nt = 0; nt < 4; nt++) {
            int col = ntile * 128 + wn + nt * 8 + 2 * tq;
            float2 bb = *(const float2*)&bp[col];
            size_t r0 = (size_t)(m0 + wm + gid);
            *(float2*)&out[r0 * C_ + col] =
                make_float2(acc[nt][0] + bb.x, acc[nt][1] + bb.y);
            *(float2*)&out[(r0 + 8) * C_ + col] =
                make_float2(acc[nt][2] + bb.x, acc[nt][3] + bb.y);
        }
    }
}

// ---------------------------------------------------------------------------
extern "C" void kernel_launch(void* const* d_in, const int* in_sizes, int n_in,
                              void* d_out, int out_size)
{
    const float* x      = (const float*)d_in[0];
    const float* W_attn = (const float*)d_in[1];
    const float* b_attn = (const float*)d_in[2];
    const float* W_proj = (const float*)d_in[3];
    const float* b_proj = (const float*)d_in[4];
    float* out  = (float*)d_out;
    half*  Hbuf = (half*)d_out;

    const int kvq_smem  = 128 * 68 * 4;                    // 34816
    const int proj_smem = 32 * 1032 * 2 + 128 * 66 * 2;    // 82944

    cudaFuncSetAttribute(proj_kernel, cudaFuncAttributeMaxDynamicSharedMemorySize, proj_smem);

    for (int wv = 0; wv < 2; wv++) {
        const int hbase = wv * 8;
        kvq_kernel<<<dim3(24, M_ / 128), 256, kvq_smem>>>(x, W_attn, b_attn, Hbuf, hbase);
        flash_mma<<<dim3(T_ / 64, B_, 8), 256>>>(Hbuf, hbase);
    }

    proj_kernel<<<128, 256, proj_smem>>>(W_proj, b_proj, out);
}

// round 17
// speedup vs baseline: 3.3106x; 1.0161x over previous
#include <cuda_runtime.h>
#include <cuda_fp16.h>
#include <math.h>
#include <string.h>

// Problem constants
#define B_  2
#define T_  2048
#define C_  1024
#define H_  16
#define D_  64
#define M_  (B_*T_)          // 4096
#define N3_ (3*C_)           // 3072

// NO __device__ globals, NO static initializers (R2-R10: any module data
// segment triggers a 128 MiB driver slab inside the checkpointed run).
// All scratch lives in d_out (16 MiB = 4096 rows x 2048 halfs), in "strips":
// strip s of row m = halfs [m*2048 + s*128, +128).
//
// 2 head-waves of 8. Per wave (local head hl = h - hbase):
//   K fp16 -> strip hl, off 0;  V fp16 -> strip hl, off 64
//   Q fp16 -> strip 8+(h>>1), off (h&1)*64   (wave0: s8-11, wave1: s12-15)
//   y fp16 OVERWRITES Q in place. proj reads y at strip 8+(h>>1), half h&1.

// ---------------------------------------------------------------------------
// helpers
// ---------------------------------------------------------------------------
__device__ __forceinline__ unsigned h2_as_u32(half2 v)
{
    unsigned u;
    memcpy(&u, &v, 4);
    return u;
}

__device__ __forceinline__ void cp_async16(void* smem_dst, const void* gsrc)
{
    unsigned saddr = (unsigned)__cvta_generic_to_shared(smem_dst);
    asm volatile("cp.async.ca.shared.global [%0], [%1], 16;"
                 :: "r"(saddr), "l"(gsrc));
}
__device__ __forceinline__ void cp_commit()
{
    asm volatile("cp.async.commit_group;");
}
__device__ __forceinline__ void cp_wait_all()
{
    asm volatile("cp.async.wait_group 0;");
}

__device__ __forceinline__ void mma16816(
    float c[4], const unsigned a[4], unsigned b0, unsigned b1)
{
    asm volatile(
        "mma.sync.aligned.m16n8k16.row.col.f32.f16.f16.f32 "
        "{%0,%1,%2,%3}, {%4,%5,%6,%7}, {%8,%9}, {%0,%1,%2,%3};"
        : "+f"(c[0]), "+f"(c[1]), "+f"(c[2]), "+f"(c[3])
        : "r"(a[0]), "r"(a[1]), "r"(a[2]), "r"(a[3]), "r"(b0), "r"(b1));
}

// ---------------------------------------------------------------------------
// kvq (tensor-core): unchanged from R16 (verified).
// ---------------------------------------------------------------------------
__global__ __launch_bounds__(256) void kvq_kernel(
    const float* __restrict__ x, const float* __restrict__ Wa,
    const float* __restrict__ ba, half* __restrict__ Hbuf, int hbase)
{
    extern __shared__ char dsm[];
    half*  Xs = (half*)dsm;             // [128][66]
    half*  Ws = Xs + 128 * 66;          // [64][66]
    float* Es = (float*)dsm;            // [128][68] overlay

    const int tid  = threadIdx.x;
    const int lane = tid & 31;
    const int w    = tid >> 5;
    const int gid  = lane >> 2;
    const int tq   = lane & 3;
    const int wm   = (w >> 1) * 32;
    const int wn   = (w & 1) * 32;

    const int m0   = blockIdx.y * 128;
    const int hl   = blockIdx.x / 3;
    const int kind = blockIdx.x % 3;              // 0=K, 1=V, 2=Q
    const int h    = hbase + hl;
    const int n0   = (kind == 0 ? C_ : (kind == 1 ? 2 * C_ : 0)) + h * 64;
    const int s    = (kind == 2) ? (8 + (h >> 1)) : hl;
    const int off  = (kind == 2) ? ((h & 1) * 64) : (kind == 1 ? 64 : 0);

    float acc[2][4][4];
    #pragma unroll
    for (int mt = 0; mt < 2; mt++)
        #pragma unroll
        for (int nt = 0; nt < 4; nt++)
            #pragma unroll
            for (int c = 0; c < 4; c++) acc[mt][nt][c] = 0.f;

    for (int k0 = 0; k0 < C_; k0 += 64) {
        __syncthreads();
        #pragma unroll
        for (int i = 0; i < 8; i++) {
            int f  = tid + i * 256;
            int m  = f >> 4;
            int kc = (f & 15) * 4;
            float4 a4 = *(const float4*)&x[(size_t)(m0 + m) * C_ + k0 + kc];
            *(half2*)&Xs[m * 66 + kc]     = __floats2half2_rn(a4.x, a4.y);
            *(half2*)&Xs[m * 66 + kc + 2] = __floats2half2_rn(a4.z, a4.w);
        }
        #pragma unroll
        for (int i = 0; i < 8; i++) {
            int f  = tid + i * 256;
            int n2 = f & 31;
            int k  = f >> 5;
            float2 wv = *(const float2*)&Wa[(size_t)(k0 + k) * N3_ + n0 + 2 * n2];
            Ws[(2 * n2 + 0) * 66 + k] = __float2half_rn(wv.x);
            Ws[(2 * n2 + 1) * 66 + k] = __float2half_rn(wv.y);
        }
        __syncthreads();

        #pragma unroll
        for (int kt = 0; kt < 4; kt++) {
            unsigned af[2][4];
            #pragma unroll
            for (int mt = 0; mt < 2; mt++) {
                int row = wm + mt * 16 + gid;
                int col = kt * 16 + 2 * tq;
                af[mt][0] = *(const unsigned*)&Xs[row * 66 + col];
                af[mt][1] = *(const unsigned*)&Xs[(row + 8) * 66 + col];
                af[mt][2] = *(const unsigned*)&Xs[row * 66 + col + 8];
                af[mt][3] = *(const unsigned*)&Xs[(row + 8) * 66 + col + 8];
            }
            #pragma unroll
            for (int nt = 0; nt < 4; nt++) {
                int nrow = (wn + nt * 8 + gid) * 66 + kt * 16 + 2 * tq;
                unsigned b0 = *(const unsigned*)&Ws[nrow];
                unsigned b1 = *(const unsigned*)&Ws[nrow + 8];
                mma16816(acc[0][nt], af[0], b0, b1);
                mma16816(acc[1][nt], af[1], b0, b1);
            }
        }
    }

    __syncthreads();
    #pragma unroll
    for (int mt = 0; mt < 2; mt++)
        #pragma unroll
        for (int nt = 0; nt < 4; nt++) {
            int r0 = wm + mt * 16 + gid;
            int c  = wn + nt * 8 + 2 * tq;
            *(float2*)&Es[r0 * 68 + c]       = make_float2(acc[mt][nt][0], acc[mt][nt][1]);
            *(float2*)&Es[(r0 + 8) * 68 + c] = make_float2(acc[mt][nt][2], acc[mt][nt][3]);
        }
    __syncthreads();

    const int tx = tid & 15;
    const int ty = tid >> 4;

    float4 bv = *(const float4*)&ba[n0 + tx * 4];
    const float bias_c[4] = {bv.x, bv.y, bv.z, bv.w};

    if (kind == 1) {
        #pragma unroll
        for (int r = 0; r < 8; r++) {
            float4 v4 = *(float4*)&Es[(ty * 8 + r) * 68 + tx * 4];
            const size_t idx = (size_t)(m0 + ty * 8 + r) * 2048 + s * 128 + off + tx * 4;
            *(half2*)&Hbuf[idx]     = __floats2half2_rn(v4.x + bias_c[0], v4.y + bias_c[1]);
            *(half2*)&Hbuf[idx + 2] = __floats2half2_rn(v4.z + bias_c[2], v4.w + bias_c[3]);
        }
        return;
    }

    float csv[4], snv[4];
    #pragma unroll
    for (int c = 0; c < 4; c++) {
        int j = ((tx & 7) * 4) + c;
        float ang = (float)h * __expf(-(float)j * 0.28782313662425572f);
        __sincosf(ang, &snv[c], &csv[c]);
    }
    const float scale = (kind == 2) ? 0.125f : 1.0f;
    const bool lo_half = (tx < 8);

    #pragma unroll
    for (int r = 0; r < 8; r++) {
        float4 v4 = *(float4*)&Es[(ty * 8 + r) * 68 + tx * 4];
        float v0 = v4.x + bias_c[0];
        float v1 = v4.y + bias_c[1];
        float v2 = v4.z + bias_c[2];
        float v3 = v4.w + bias_c[3];

        float ss = v0 * v0 + v1 * v1 + v2 * v2 + v3 * v3;
        ss += __shfl_xor_sync(~0u, ss, 1);
        ss += __shfl_xor_sync(~0u, ss, 2);
        ss += __shfl_xor_sync(~0u, ss, 4);
        ss += __shfl_xor_sync(~0u, ss, 8);
        float sc = rsqrtf(ss * (1.0f / 64.0f) + 1.1920929e-07f);
        v0 *= sc; v1 *= sc; v2 *= sc; v3 *= sc;

        float p0 = __shfl_xor_sync(~0u, v0, 8);
        float p1 = __shfl_xor_sync(~0u, v1, 8);
        float p2 = __shfl_xor_sync(~0u, v2, 8);
        float p3 = __shfl_xor_sync(~0u, v3, 8);

        float o0, o1, o2, o3;
        if (lo_half) {
            o0 = v0 * csv[0] + p0 * snv[0];
            o1 = v1 * csv[1] + p1 * snv[1];
            o2 = v2 * csv[2] + p2 * snv[2];
            o3 = v3 * csv[3] + p3 * snv[3];
        } else {
            o0 = v0 * csv[0] - p0 * snv[0];
            o1 = v1 * csv[1] - p1 * snv[1];
            o2 = v2 * csv[2] - p2 * snv[2];
            o3 = v3 * csv[3] - p3 * snv[3];
        }

        const size_t idx = (size_t)(m0 + ty * 8 + r) * 2048 + s * 128 + off + tx * 4;
        *(half2*)&Hbuf[idx]     = __floats2half2_rn(o0 * scale, o1 * scale);
        *(half2*)&Hbuf[idx + 2] = __floats2half2_rn(o2 * scale, o3 * scale);
    }
}

// ---------------------------------------------------------------------------
// FA2 + software-pipelined flash (one wave of 8 heads).
// 8 warps = 4(q) x 2(j), warp-private (m,l,O), P in registers.
// K double-buffered via cp.async; V double-buffered via register pipeline
// (load next tile's V into regs before compute, transpose-store after PV).
// ONE __syncthreads per KV tile. q-tiles reversed; y overwrites Q in place.
// ---------------------------------------------------------------------------
__global__ __launch_bounds__(256, 2) void flash_mma(half* __restrict__ Hbuf, int hbase)
{
    __shared__ __align__(16) half Qh[64 * 72];
    __shared__ __align__(16) half Kh[2][64 * 72];
    __shared__ __align__(16) half Vt[2][64 * 72];   // Vt[d][j]
    __shared__ float Msm[2][64];
    __shared__ float Lsm[2][64];
    float* Osm = (float*)&Kh[0][0];                 // epilogue overlay [64][68]

    const int tid  = threadIdx.x;
    const int lane = tid & 31;
    const int w    = tid >> 5;
    const int gid  = lane >> 2;
    const int tq   = lane & 3;
    const int wq   = (w >> 1) * 16;      // warp q offset
    const int wc   = w & 1;              // warp column (j-slice id)
    const int wk   = wc * 32;            // warp j offset

    const int hl = blockIdx.z;
    const int h  = hbase + hl;
    const int b  = blockIdx.y;
    const int qx = 31 - blockIdx.x;      // reversed: longest first
    const int q0 = qx * 64;
    const int kvs = hl;
    const int qs  = 8 + (h >> 1);
    const int qoff = (h & 1) * 64;

    // per-thread load coordinates (fixed across tiles)
    const int kr = tid >> 3;             // K row (0..31) for i-th half handled below
    const int kc = (tid & 7) * 8;        // K col (halfs)
    const int vr = tid >> 5;             // V row base
    const int vc2 = tid & 31;            // V half2 col

    // ---- load Q tile ----
    #pragma unroll
    for (int i = 0; i < 2; i++) {
        int f = tid + i * 256;
        int r = f >> 3;
        int c = (f & 7) * 8;
        *(int4*)&Qh[r * 72 + c] =
            *(const int4*)&Hbuf[(size_t)(b * 2048 + q0 + r) * 2048 + qs * 128 + qoff + c];
    }

    // ---- prologue: tile 0 into buffer 0 ----
    {
        #pragma unroll
        for (int i = 0; i < 2; i++) {
            int r = kr + i * 32;
            cp_async16(&Kh[0][r * 72 + kc],
                       &Hbuf[(size_t)(b * 2048 + r) * 2048 + kvs * 128 + kc]);
        }
        cp_commit();
        #pragma unroll
        for (int i = 0; i < 8; i++) {
            int r = vr + i * 8;
            half2 v = *(const half2*)&Hbuf[(size_t)(b * 2048 + r) * 2048 + kvs * 128 + 64 + vc2 * 2];
            Vt[0][(2 * vc2 + 0) * 72 + r] = __low2half(v);
            Vt[0][(2 * vc2 + 1) * 72 + r] = __high2half(v);
        }
        cp_wait_all();
        __syncthreads();
    }

    float m0v = -1e30f, m1v = -1e30f, l0v = 0.f, l1v = 0.f;
    float oa[8][4];
    #pragma unroll
    for (int dt = 0; dt < 8; dt++)
        #pragma unroll
        for (int c = 0; c < 4; c++) oa[dt][c] = 0.f;

    const int ntiles = qx + 1;
    for (int it = 0; it < ntiles; it++) {
        const int cur = it & 1;
        const int nxt = cur ^ 1;
        const bool pre = (it + 1 < ntiles);
        unsigned vreg[8];

        // ---- prefetch tile it+1 (latency hidden behind this tile's mmas) ----
        if (pre) {
            const int k1 = (it + 1) * 64;
            #pragma unroll
            for (int i = 0; i < 2; i++) {
                int r = kr + i * 32;
                cp_async16(&Kh[nxt][r * 72 + kc],
                           &Hbuf[(size_t)(b * 2048 + k1 + r) * 2048 + kvs * 128 + kc]);
            }
            cp_commit();
            #pragma unroll
            for (int i = 0; i < 8; i++) {
                int r = vr + i * 8;
                vreg[i] = *(const unsigned*)&Hbuf[(size_t)(b * 2048 + k1 + r) * 2048 + kvs * 128 + 64 + vc2 * 2];
            }
        }

        const int k0 = it * 64;
        const half* Kc = &Kh[cur][0];
        const half* Vc = &Vt[cur][0];

        // ---- score S = Q K^T (warp: 16q x 32j at wk) ----
        float sacc[4][4];
        #pragma unroll
        for (int nt = 0; nt < 4; nt++)
            #pragma unroll
            for (int c = 0; c < 4; c++) sacc[nt][c] = 0.f;

        #pragma unroll
        for (int kt = 0; kt < 4; kt++) {
            int col = kt * 16 + 2 * tq;
            unsigned aqf[4];
            aqf[0] = *(const unsigned*)&Qh[(wq + gid) * 72 + col];
            aqf[1] = *(const unsigned*)&Qh[(wq + gid + 8) * 72 + col];
            aqf[2] = *(const unsigned*)&Qh[(wq + gid) * 72 + col + 8];
            aqf[3] = *(const unsigned*)&Qh[(wq + gid + 8) * 72 + col + 8];
            #pragma unroll
            for (int nt = 0; nt < 4; nt++) {
                int krow = (wk + nt * 8 + gid) * 72 + col;
                unsigned bk0 = *(const unsigned*)&Kc[krow];
                unsigned bk1 = *(const unsigned*)&Kc[krow + 8];
                mma16816(sacc[nt], aqf, bk0, bk1);
            }
        }

        if (k0 == q0) {
            #pragma unroll
            for (int nt = 0; nt < 4; nt++)
                #pragma unroll
                for (int c = 0; c < 4; c++) {
                    int col = wk + nt * 8 + 2 * tq + (c & 1);
                    int row = wq + gid + ((c >> 1) * 8);
                    if (col > row) sacc[nt][c] = -1e30f;
                }
        }

        // ---- warp-private online softmax ----
        float tm0 = -1e30f, tm1 = -1e30f;
        #pragma unroll
        for (int nt = 0; nt < 4; nt++) {
            tm0 = fmaxf(tm0, fmaxf(sacc[nt][0], sacc[nt][1]));
            tm1 = fmaxf(tm1, fmaxf(sacc[nt][2], sacc[nt][3]));
        }
        tm0 = fmaxf(tm0, __shfl_xor_sync(~0u, tm0, 1));
        tm0 = fmaxf(tm0, __shfl_xor_sync(~0u, tm0, 2));
        tm1 = fmaxf(tm1, __shfl_xor_sync(~0u, tm1, 1));
        tm1 = fmaxf(tm1, __shfl_xor_sync(~0u, tm1, 2));
        float mn0 = fmaxf(m0v, tm0);
        float mn1 = fmaxf(m1v, tm1);
        float alpha0 = __expf(m0v - mn0);
        float alpha1 = __expf(m1v - mn1);
        m0v = mn0; m1v = mn1;

        float ts0 = 0.f, ts1 = 0.f;
        unsigned plo[4], phi[4];
        #pragma unroll
        for (int nt = 0; nt < 4; nt++) {
            float e0 = __expf(sacc[nt][0] - mn0);
            float e1 = __expf(sacc[nt][1] - mn0);
            float e2 = __expf(sacc[nt][2] - mn1);
            float e3 = __expf(sacc[nt][3] - mn1);
            ts0 += e0 + e1;
            ts1 += e2 + e3;
            plo[nt] = h2_as_u32(__floats2half2_rn(e0, e1));
            phi[nt] = h2_as_u32(__floats2half2_rn(e2, e3));
        }
        ts0 += __shfl_xor_sync(~0u, ts0, 1);
        ts0 += __shfl_xor_sync(~0u, ts0, 2);
        ts1 += __shfl_xor_sync(~0u, ts1, 1);
        ts1 += __shfl_xor_sync(~0u, ts1, 2);
        l0v = l0v * alpha0 + ts0;
        l1v = l1v * alpha1 + ts1;

        #pragma unroll
        for (int dt = 0; dt < 8; dt++) {
            oa[dt][0] *= alpha0;
            oa[dt][1] *= alpha0;
            oa[dt][2] *= alpha1;
            oa[dt][3] *= alpha1;
        }

        // ---- O += P V (P in registers; warp: 16q x 64d over its 32 j) ----
        #pragma unroll
        for (int jt = 0; jt < 2; jt++) {
            unsigned ap[4];
            ap[0] = plo[jt * 2 + 0];
            ap[1] = phi[jt * 2 + 0];
            ap[2] = plo[jt * 2 + 1];
            ap[3] = phi[jt * 2 + 1];
            #pragma unroll
            for (int dt = 0; dt < 8; dt++) {
                int vrow = (dt * 8 + gid) * 72 + wk + jt * 16 + 2 * tq;
                unsigned bv0 = *(const unsigned*)&Vc[vrow];
                unsigned bv1 = *(const unsigned*)&Vc[vrow + 8];
                mma16816(oa[dt], ap, bv0, bv1);
            }
        }

        // ---- drain pipeline: store V(it+1), wait K(it+1), sync ----
        if (pre) {
            #pragma unroll
            for (int i = 0; i < 8; i++) {
                int r = vr + i * 8;
                half2 v;
                memcpy(&v, &vreg[i], 4);
                Vt[nxt][(2 * vc2 + 0) * 72 + r] = __low2half(v);
                Vt[nxt][(2 * vc2 + 1) * 72 + r] = __high2half(v);
            }
            cp_wait_all();
        }
        __syncthreads();
    }

    // ---- epilogue: merge the 2 warp columns, normalize, write y ----
    const int row0 = wq + gid;
    const int row1 = row0 + 8;
    if (tq == 0) {
        Msm[wc][row0] = m0v;
        Msm[wc][row1] = m1v;
    }
    __syncthreads();
    float mf0 = fmaxf(Msm[0][row0], Msm[1][row0]);
    float mf1 = fmaxf(Msm[0][row1], Msm[1][row1]);
    float fac0 = __expf(m0v - mf0);
    float fac1 = __expf(m1v - mf1);
    if (tq == 0) {
        Lsm[wc][row0] = l0v * fac0;
        Lsm[wc][row1] = l1v * fac1;
    }
    #pragma unroll
    for (int dt = 0; dt < 8; dt++) {
        oa[dt][0] *= fac0;
        oa[dt][1] *= fac0;
        oa[dt][2] *= fac1;
        oa[dt][3] *= fac1;
    }
    __syncthreads();
    float lt0 = Lsm[0][row0] + Lsm[1][row0];
    float lt1 = Lsm[0][row1] + Lsm[1][row1];
    if (wc == 1) {
        #pragma unroll
        for (int dt = 0; dt < 8; dt++) {
            int col = dt * 8 + 2 * tq;
            *(float2*)&Osm[row0 * 68 + col] = make_float2(oa[dt][0], oa[dt][1]);
            *(float2*)&Osm[row1 * 68 + col] = make_float2(oa[dt][2], oa[dt][3]);
        }
    }
    __syncthreads();
    if (wc == 0) {
        float inv0 = 1.0f / lt0;
        float inv1 = 1.0f / lt1;
        const size_t r0g = (size_t)(b * 2048 + q0 + row0);
        const size_t r1g = r0g + 8;
        #pragma unroll
        for (int dt = 0; dt < 8; dt++) {
            int col = dt * 8 + 2 * tq;
            float2 p0 = *(float2*)&Osm[row0 * 68 + col];
            float2 p1 = *(float2*)&Osm[row1 * 68 + col];
            *(half2*)&Hbuf[r0g * 2048 + qs * 128 + qoff + col] =
                __floats2half2_rn((oa[dt][0] + p0.x) * inv0, (oa[dt][1] + p0.y) * inv0);
            *(half2*)&Hbuf[r1g * 2048 + qs * 128 + qoff + col] =
                __floats2half2_rn((oa[dt][2] + p1.x) * inv1, (oa[dt][3] + p1.y) * inv1);
        }
    }
}

// ---------------------------------------------------------------------------
// proj (tensor-core, in-place): unchanged from R16 (verified).
// ---------------------------------------------------------------------------
__global__ __launch_bounds__(256) void proj_kernel(
    const float* __restrict__ Wp, const float* __restrict__ bp,
    float* __restrict__ out)
{
    extern __shared__ char dsm[];
    half* ysm = (half*)dsm;             // [32][1032]
    half* Ws  = ysm + 32 * 1032;        // [128][66]

    const half* Hbuf = (const half*)out;
    const int tid  = threadIdx.x;
    const int lane = tid & 31;
    const int w    = tid >> 5;
    const int gid  = lane >> 2;
    const int tq   = lane & 3;
    const int wm   = (w >> 2) * 16;
    const int wn   = (w & 3) * 32;
    const int m0   = blockIdx.x * 32;

    #pragma unroll
    for (int i = 0; i < 64; i++) {
        int f  = tid + i * 256;
        int r  = f >> 9;
        int c2 = f & 511;
        int hh = c2 >> 5;
        int d2 = c2 & 31;
        int ys = 8 + (hh >> 1);
        int yh = hh & 1;
        half2 v = *(const half2*)&Hbuf[(size_t)(m0 + r) * 2048 + ys * 128 + yh * 64 + d2 * 2];
        *(half2*)&ysm[r * 1032 + c2 * 2] = v;
    }
    __syncthreads();

    for (int ntile = 0; ntile < 8; ntile++) {
        float acc[4][4];
        #pragma unroll
        for (int nt = 0; nt < 4; nt++)
            #pragma unroll
            for (int c = 0; c < 4; c++) acc[nt][c] = 0.f;

        for (int k0 = 0; k0 < C_; k0 += 64) {
            __syncthreads();
            #pragma unroll
            for (int i = 0; i < 16; i++) {
                int f  = tid + i * 256;
                int n2 = f & 63;
                int k  = f >> 6;
                float2 wv = *(const float2*)&Wp[(size_t)(k0 + k) * C_ + ntile * 128 + 2 * n2];
                Ws[(2 * n2 + 0) * 66 + k] = __float2half_rn(wv.x);
                Ws[(2 * n2 + 1) * 66 + k] = __float2half_rn(wv.y);
            }
            __syncthreads();

            #pragma unroll
            for (int kt = 0; kt < 4; kt++) {
                int col = k0 + kt * 16 + 2 * tq;
                unsigned af[4];
                af[0] = *(const unsigned*)&ysm[(wm + gid) * 1032 + col];
                af[1] = *(const unsigned*)&ysm[(wm + gid + 8) * 1032 + col];
                af[2] = *(const unsigned*)&ysm[(wm + gid) * 1032 + col + 8];
                af[3] = *(const unsigned*)&ysm[(wm + gid + 8) * 1032 + col + 8];
                #pragma unroll
                for (int nt = 0; nt < 4; nt++) {
                    int nrow = (wn + nt * 8 + gid) * 66 + kt * 16 + 2 * tq;
                    unsigned b0 = *(const unsigned*)&Ws[nrow];
                    unsigned b1 = *(const unsigned*)&Ws[nrow + 8];
                    mma16816(acc[nt], af, b0, b1);
                }
            }
        }

        #pragma unroll
        for (int nt = 0; nt < 4; nt++) {
            int col = ntile * 128 + wn + nt * 8 + 2 * tq;
            float2 bb = *(const float2*)&bp[col];
            size_t r0 = (size_t)(m0 + wm + gid);
            *(float2*)&out[r0 * C_ + col] =
                make_float2(acc[nt][0] + bb.x, acc[nt][1] + bb.y);
            *(float2*)&out[(r0 + 8) * C_ + col] =
                make_float2(acc[nt][2] + bb.x, acc[nt][3] + bb.y);
        }
    }
}

// ---------------------------------------------------------------------------
extern "C" void kernel_launch(void* const* d_in, const int* in_sizes, int n_in,
                              void* d_out, int out_size)
{
    const float* x      = (const float*)d_in[0];
    const float* W_attn = (const float*)d_in[1];
    const float* b_attn = (const float*)d_in[2];
    const float* W_proj = (const float*)d_in[3];
    const float* b_proj = (const float*)d_in[4];
    float* out  = (float*)d_out;
    half*  Hbuf = (half*)d_out;

    const int kvq_smem  = 128 * 68 * 4;                    // 34816
    const int proj_smem = 32 * 1032 * 2 + 128 * 66 * 2;    // 82944

    cudaFuncSetAttribute(proj_kernel, cudaFuncAttributeMaxDynamicSharedMemorySize, proj_smem);

    for (int wv = 0; wv < 2; wv++) {
        const int hbase = wv * 8;
        kvq_kernel<<<dim3(24, M_ / 128), 256, kvq_smem>>>(x, W_attn, b_attn, Hbuf, hbase);
        flash_mma<<<dim3(T_ / 64, B_, 8), 256>>>(Hbuf, hbase);
    }

    proj_kernel<<<128, 256, proj_smem>>>(W_proj, b_proj, out);
}